// round 1
// baseline (speedup 1.0000x reference)
#include <cuda_runtime.h>
#include <cstddef>

// Problem constants
#define NB    16
#define NS    1024
#define ND    384      // H * HD
#define NH    6
#define NHD   64
#define NK    9
#define NKH   54       // K * H
#define NOUT  384
#define NPAD  4        // K/2

// Tiling
#define TS       32    // seq rows per block
#define NTHREADS 256
#define DCHUNK   16    // K-chunk of Wp staged in smem

// Transposed Wp scratch: WpT[d][o]  (device global; no allocation allowed)
__device__ float g_WpT[ND * NOUT];

__global__ void wp_transpose_kernel(const float* __restrict__ Wp) {
    int i = blockIdx.x * blockDim.x + threadIdx.x;
    if (i < NOUT * ND) {
        int o = i / ND;
        int d = i % ND;
        g_WpT[d * NOUT + o] = Wp[i];
    }
}

// One block handles (batch b, 32 consecutive seq rows).
// Phases:
//  P1: sA = q*ks tile                [32 x 384]
//  P2: logits = sA @ Wk^T + bk       [32 x 54]   (warp-split dot products)
//  P3: softmax over K=9 per head     in-place in sL
//  P4: conv: sA = sum_k dk * v_win   (overwrites sA)
//  P5: out = sA @ WpT + bp           (register-blocked FFMA GEMM)
__global__ __launch_bounds__(NTHREADS) void sdca_kernel(
    const float* __restrict__ q,
    const float* __restrict__ ks,
    const float* __restrict__ v,
    const float* __restrict__ Wk,
    const float* __restrict__ bk,
    const float* __restrict__ bp,
    float* __restrict__ out)
{
    extern __shared__ float smem[];
    float* sA = smem;                    // TS*ND     = 12288 floats
    float* sW = sA + TS * ND;            // DCHUNK*NOUT = 6144 floats
    float* sL = sW + DCHUNK * NOUT;      // TS*NKH    = 1728 floats

    const int tid = threadIdx.x;
    const int b  = blockIdx.x / (NS / TS);
    const int s0 = (blockIdx.x % (NS / TS)) * TS;

    // ---------- P1: g = q * ks ----------
    {
        const float* qb = q  + ((size_t)b * NS + s0) * ND;
        const float* kb = ks + ((size_t)b * NS + s0) * ND;
        for (int i = tid; i < TS * ND; i += NTHREADS)
            sA[i] = qb[i] * kb[i];
    }
    __syncthreads();

    // ---------- P2: logits[r][o] = dot(g[r,:], Wk[o,:]) + bk[o] ----------
    // Warp w owns rows 4w..4w+3. Lane l covers d = l, l+32, ..., l+352.
    {
        const int w    = tid >> 5;
        const int lane = tid & 31;
        float gr[4][12];
        #pragma unroll
        for (int rr = 0; rr < 4; rr++)
            #pragma unroll
            for (int i = 0; i < 12; i++)
                gr[rr][i] = sA[(w * 4 + rr) * ND + lane + 32 * i];

        for (int o = 0; o < NKH; o++) {
            float a0 = 0.f, a1 = 0.f, a2 = 0.f, a3 = 0.f;
            const float* wk = Wk + o * ND + lane;
            #pragma unroll
            for (int i = 0; i < 12; i++) {
                float wv = wk[32 * i];
                a0 = fmaf(gr[0][i], wv, a0);
                a1 = fmaf(gr[1][i], wv, a1);
                a2 = fmaf(gr[2][i], wv, a2);
                a3 = fmaf(gr[3][i], wv, a3);
            }
            #pragma unroll
            for (int off = 16; off > 0; off >>= 1) {
                a0 += __shfl_xor_sync(0xffffffffu, a0, off);
                a1 += __shfl_xor_sync(0xffffffffu, a1, off);
                a2 += __shfl_xor_sync(0xffffffffu, a2, off);
                a3 += __shfl_xor_sync(0xffffffffu, a3, off);
            }
            if (lane == 0) {
                float bko = bk[o];
                sL[(w * 4 + 0) * NKH + o] = a0 + bko;
                sL[(w * 4 + 1) * NKH + o] = a1 + bko;
                sL[(w * 4 + 2) * NKH + o] = a2 + bko;
                sL[(w * 4 + 3) * NKH + o] = a3 + bko;
            }
        }
    }
    __syncthreads();

    // ---------- P3: softmax over the K=9 taps of each (row, head) ----------
    // logits o index = h*K + k  (reshape (H, K))
    if (tid < TS * NH) {
        int r = tid / NH;
        int h = tid % NH;
        float* p = sL + r * NKH + h * NK;
        float m = p[0];
        #pragma unroll
        for (int k = 1; k < NK; k++) m = fmaxf(m, p[k]);
        float e[NK];
        float ssum = 0.f;
        #pragma unroll
        for (int k = 0; k < NK; k++) { e[k] = __expf(p[k] - m); ssum += e[k]; }
        float inv = 1.0f / ssum;
        #pragma unroll
        for (int k = 0; k < NK; k++) p[k] = e[k] * inv;
    }
    __syncthreads();

    // ---------- P4: dynamic conv, overwrite sA with conv output ----------
    {
        const float* vb = v + (size_t)b * NS * ND;
        for (int i = tid; i < TS * ND; i += NTHREADS) {
            int r = i / ND;
            int c = i % ND;
            int h = c / NHD;
            const float* dkp = sL + r * NKH + h * NK;
            int s = s0 + r;
            float acc = 0.f;
            #pragma unroll
            for (int k = 0; k < NK; k++) {
                int sr = s + k - NPAD;
                float vv = (sr >= 0 && sr < NS) ? vb[(size_t)sr * ND + c] : 0.f;
                acc = fmaf(dkp[k], vv, acc);
            }
            sA[i] = acc;
        }
    }
    __syncthreads();

    // ---------- P5: out = sA @ WpT + bp  (32 x 384 x 384) ----------
    // Thread (tx, ty): rows 4*ty..4*ty+3, cols tx + 32*j (j=0..11). 48 accs.
    {
        const int tx = tid & 31;
        const int ty = tid >> 5;
        float acc[4][12];
        #pragma unroll
        for (int rr = 0; rr < 4; rr++)
            #pragma unroll
            for (int j = 0; j < 12; j++)
                acc[rr][j] = 0.f;

        for (int d0 = 0; d0 < ND; d0 += DCHUNK) {
            // stage WpT[d0:d0+16, :] into smem (coalesced, L2-resident)
            for (int i = tid; i < DCHUNK * NOUT; i += NTHREADS)
                sW[i] = g_WpT[d0 * NOUT + i];
            __syncthreads();

            #pragma unroll
            for (int dd = 0; dd < DCHUNK; dd++) {
                float a0 = sA[(ty * 4 + 0) * ND + d0 + dd];
                float a1 = sA[(ty * 4 + 1) * ND + d0 + dd];
                float a2 = sA[(ty * 4 + 2) * ND + d0 + dd];
                float a3 = sA[(ty * 4 + 3) * ND + d0 + dd];
                float wreg[12];
                #pragma unroll
                for (int j = 0; j < 12; j++)
                    wreg[j] = sW[dd * NOUT + tx + 32 * j];
                #pragma unroll
                for (int j = 0; j < 12; j++) {
                    acc[0][j] = fmaf(a0, wreg[j], acc[0][j]);
                    acc[1][j] = fmaf(a1, wreg[j], acc[1][j]);
                    acc[2][j] = fmaf(a2, wreg[j], acc[2][j]);
                    acc[3][j] = fmaf(a3, wreg[j], acc[3][j]);
                }
            }
            __syncthreads();
        }

        // epilogue: add bias, coalesced store
        float* ob = out + ((size_t)b * NS + s0) * NOUT;
        #pragma unroll
        for (int j = 0; j < 12; j++) {
            float bpj = bp[tx + 32 * j];
            #pragma unroll
            for (int rr = 0; rr < 4; rr++)
                ob[(size_t)(ty * 4 + rr) * NOUT + tx + 32 * j] = acc[rr][j] + bpj;
        }
    }
}

extern "C" void kernel_launch(void* const* d_in, const int* in_sizes, int n_in,
                              void* d_out, int out_size) {
    const float* q  = (const float*)d_in[0];
    const float* ks = (const float*)d_in[1];
    const float* v  = (const float*)d_in[2];
    const float* Wk = (const float*)d_in[3];
    const float* bk = (const float*)d_in[4];
    const float* Wp = (const float*)d_in[5];
    const float* bp = (const float*)d_in[6];
    float* out = (float*)d_out;

    (void)in_sizes; (void)n_in; (void)out_size;

    // 1) transpose Wp -> WpT (coalesced GEMM B-operand)
    wp_transpose_kernel<<<(NOUT * ND + 255) / 256, 256>>>(Wp);

    // 2) fused main kernel
    const int smem_bytes = (TS * ND + DCHUNK * NOUT + TS * NKH) * (int)sizeof(float); // 80640
    cudaFuncSetAttribute(sdca_kernel, cudaFuncAttributeMaxDynamicSharedMemorySize, smem_bytes);
    dim3 grid(NB * (NS / TS));  // 512 blocks
    sdca_kernel<<<grid, NTHREADS, smem_bytes>>>(q, ks, v, Wk, bk, bp, out);
}

// round 2
// speedup vs baseline: 1.4876x; 1.4876x over previous
#include <cuda_runtime.h>
#include <cstddef>

// Problem constants
#define NB    16
#define NS    1024
#define ND    384      // H * HD
#define NH    6
#define NHD   64
#define NK    9
#define NKH   54       // K * H
#define NKHP  64       // padded logits width
#define NOUT  384
#define NPAD  4        // K/2

// Tiling
#define TS       32    // seq rows per block
#define NTHREADS 256
#define DCHUNK   32    // K-chunk of Wp staged in smem (P5)
#define KCHUNK   16    // K-chunk of WkT staged in smem (P2)
#define VROWS    24    // v rows staged per conv half-pass

// ---------------- packed f32x2 helpers ----------------
__device__ __forceinline__ unsigned long long pack2(float x, float y) {
    unsigned long long r;
    asm("mov.b64 %0, {%1, %2};" : "=l"(r) : "f"(x), "f"(y));
    return r;
}
__device__ __forceinline__ void unpack2(unsigned long long v, float& x, float& y) {
    asm("mov.b64 {%0, %1}, %2;" : "=f"(x), "=f"(y) : "l"(v));
}
__device__ __forceinline__ void ffma2(unsigned long long& d,
                                      unsigned long long a,
                                      unsigned long long b) {
    asm("fma.rn.f32x2 %0, %1, %2, %0;" : "+l"(d) : "l"(a), "l"(b));
}

// Device-global scratch (no allocation allowed)
__device__ float g_WpT[ND * NOUT];        // WpT[d][o]
__device__ float g_WkT[ND * NKHP];        // WkT[d][o], o padded 54->64 with zeros

__global__ void prep_kernel(const float* __restrict__ Wp,
                            const float* __restrict__ Wk) {
    int i = blockIdx.x * blockDim.x + threadIdx.x;
    if (i < NOUT * ND) {
        int o = i / ND, d = i % ND;
        g_WpT[d * NOUT + o] = Wp[i];
    }
    if (i < ND * NKHP) {
        int d = i / NKHP, o = i % NKHP;
        g_WkT[i] = (o < NKH) ? Wk[o * ND + d] : 0.0f;
    }
}

// One block = (batch b, 32 consecutive seq rows).
// smem layout (bytes):
//   sA : 0          .. 49152   [32 x 384]  q*ks, then conv output
//   sR1: 49152      .. 98304   staging: WkT chunks / v window / Wp chunks
//   sL : 98304      .. 106496  [32 x 64]   logits / softmax weights
__global__ __launch_bounds__(NTHREADS) void sdca_kernel(
    const float* __restrict__ q,
    const float* __restrict__ ks,
    const float* __restrict__ v,
    const float* __restrict__ bk,
    const float* __restrict__ bp,
    float* __restrict__ out)
{
    extern __shared__ float smem[];
    float* sA  = smem;                       // TS*ND floats
    float* sR1 = smem + TS * ND;             // DCHUNK*NOUT floats (largest use)
    float* sL  = sR1 + DCHUNK * NOUT;        // TS*NKHP floats

    const int tid  = threadIdx.x;
    const int tx   = tid & 31;
    const int ty   = tid >> 5;
    const int b    = blockIdx.x / (NS / TS);
    const int s0   = (blockIdx.x % (NS / TS)) * TS;

    // ---------- P1: sA = q * ks (vectorized) ----------
    {
        const float4* qb = (const float4*)(q  + ((size_t)b * NS + s0) * ND);
        const float4* kb = (const float4*)(ks + ((size_t)b * NS + s0) * ND);
        float4* a4 = (float4*)sA;
        #pragma unroll
        for (int i = tid; i < TS * ND / 4; i += NTHREADS) {
            float4 qq = qb[i], kk = kb[i];
            a4[i] = make_float4(qq.x * kk.x, qq.y * kk.y, qq.z * kk.z, qq.w * kk.w);
        }
    }
    __syncthreads();

    // ---------- P2: logits[32 x 64] = sA @ WkT  (f32x2 register GEMM) ----------
    // thread: rows ty*4..+3, col pair tx -> cols 2tx, 2tx+1
    {
        unsigned long long acc2[4] = {0ull, 0ull, 0ull, 0ull};
        for (int d0 = 0; d0 < ND; d0 += KCHUNK) {
            // stage WkT[d0:d0+16, 0:64] -> sR1 (1024 floats = 256 float4)
            ((float4*)sR1)[tid] = ((const float4*)(g_WkT + d0 * NKHP))[tid];
            __syncthreads();
            #pragma unroll
            for (int dd = 0; dd < KCHUNK; dd++) {
                unsigned long long wv =
                    *(const unsigned long long*)&sR1[dd * NKHP + 2 * tx];
                #pragma unroll
                for (int rr = 0; rr < 4; rr++) {
                    float a = sA[(ty * 4 + rr) * ND + d0 + dd];
                    ffma2(acc2[rr], pack2(a, a), wv);
                }
            }
            __syncthreads();
        }
        int o0 = 2 * tx, o1 = 2 * tx + 1;
        float bk0 = (o0 < NKH) ? bk[o0] : 0.f;
        float bk1 = (o1 < NKH) ? bk[o1] : 0.f;
        #pragma unroll
        for (int rr = 0; rr < 4; rr++) {
            float x, y; unpack2(acc2[rr], x, y);
            int r = ty * 4 + rr;
            sL[r * NKHP + o0] = x + bk0;
            sL[r * NKHP + o1] = y + bk1;
        }
    }
    __syncthreads();

    // ---------- P3: softmax over K=9 taps per (row, head) ----------
    if (tid < TS * NH) {
        int r = tid / NH, h = tid % NH;
        float* p = sL + r * NKHP + h * NK;
        float m = p[0];
        #pragma unroll
        for (int k = 1; k < NK; k++) m = fmaxf(m, p[k]);
        float e[NK], ssum = 0.f;
        #pragma unroll
        for (int k = 0; k < NK; k++) { e[k] = __expf(p[k] - m); ssum += e[k]; }
        float inv = 1.0f / ssum;
        #pragma unroll
        for (int k = 0; k < NK; k++) p[k] = e[k] * inv;
    }
    __syncthreads();

    // ---------- P4: dynamic conv in two half-passes (v staged in smem) ----------
    {
        const float* vb = v + (size_t)b * NS * ND;
        #pragma unroll
        for (int half = 0; half < 2; half++) {
            // stage VROWS=24 rows of v: global rows [s0 - 4 + 16*half, +24)
            int gbase = s0 - NPAD + 16 * half;
            float4* sv4 = (float4*)sR1;
            for (int i = tid; i < VROWS * ND / 4; i += NTHREADS) {
                int rr = i / (ND / 4);
                int gr = gbase + rr;
                float4 val = make_float4(0.f, 0.f, 0.f, 0.f);
                if (gr >= 0 && gr < NS)
                    val = ((const float4*)(vb + (size_t)gr * ND))[i % (ND / 4)];
                sv4[i] = val;
            }
            __syncthreads();

            // conv rows [16*half, 16*half+16)
            for (int i = tid; i < 16 * ND; i += NTHREADS) {
                int rl = i / ND;            // 0..15
                int c  = i % ND;
                int r  = 16 * half + rl;    // block-local row
                const float* dkp = sL + r * NKHP + (c / NHD) * NK;
                float acc = 0.f;
                #pragma unroll
                for (int k = 0; k < NK; k++)
                    acc = fmaf(dkp[k], sR1[(rl + k) * ND + c], acc);
                // NOTE: write after all reads of this pass's sV region that
                // this thread does; sA row r is disjoint from sR1. Safe.
                sA[r * ND + c] = acc;
            }
            __syncthreads();
        }
    }

    // ---------- P5: out[32 x 384] = sA @ WpT + bp  (f32x2 register GEMM) ----------
    // thread: rows ty*4..+3, col pairs p = tx + 32j (j=0..5) -> cols 2p, 2p+1
    {
        unsigned long long acc2[4][6];
        #pragma unroll
        for (int rr = 0; rr < 4; rr++)
            #pragma unroll
            for (int j = 0; j < 6; j++) acc2[rr][j] = 0ull;

        for (int d0 = 0; d0 < ND; d0 += DCHUNK) {
            // stage WpT[d0:d0+32, :] -> sR1 (12288 floats = 3072 float4)
            {
                const float4* src = (const float4*)(g_WpT + d0 * NOUT);
                float4* dst = (float4*)sR1;
                #pragma unroll
                for (int i = tid; i < DCHUNK * NOUT / 4; i += NTHREADS)
                    dst[i] = src[i];
            }
            __syncthreads();

            #pragma unroll 4
            for (int dd = 0; dd < DCHUNK; dd++) {
                unsigned long long ap[4];
                #pragma unroll
                for (int rr = 0; rr < 4; rr++) {
                    float a = sA[(ty * 4 + rr) * ND + d0 + dd];
                    ap[rr] = pack2(a, a);
                }
                unsigned long long wv[6];
                #pragma unroll
                for (int j = 0; j < 6; j++)
                    wv[j] = *(const unsigned long long*)
                            &sR1[dd * NOUT + 2 * (tx + 32 * j)];
                #pragma unroll
                for (int j = 0; j < 6; j++) {
                    ffma2(acc2[0][j], ap[0], wv[j]);
                    ffma2(acc2[1][j], ap[1], wv[j]);
                    ffma2(acc2[2][j], ap[2], wv[j]);
                    ffma2(acc2[3][j], ap[3], wv[j]);
                }
            }
            __syncthreads();
        }

        // epilogue: add bias, coalesced float2 stores
        float* ob = out + ((size_t)b * NS + s0) * NOUT;
        #pragma unroll
        for (int j = 0; j < 6; j++) {
            int c = 2 * (tx + 32 * j);
            float2 bpj = *(const float2*)&bp[c];
            #pragma unroll
            for (int rr = 0; rr < 4; rr++) {
                float x, y; unpack2(acc2[rr][j], x, y);
                float2 o2 = make_float2(x + bpj.x, y + bpj.y);
                *(float2*)&ob[(size_t)(ty * 4 + rr) * NOUT + c] = o2;
            }
        }
    }
}

extern "C" void kernel_launch(void* const* d_in, const int* in_sizes, int n_in,
                              void* d_out, int out_size) {
    const float* q  = (const float*)d_in[0];
    const float* ks = (const float*)d_in[1];
    const float* v  = (const float*)d_in[2];
    const float* Wk = (const float*)d_in[3];
    const float* bk = (const float*)d_in[4];
    const float* Wp = (const float*)d_in[5];
    const float* bp = (const float*)d_in[6];
    float* out = (float*)d_out;

    (void)in_sizes; (void)n_in; (void)out_size;

    prep_kernel<<<(NOUT * ND + 255) / 256, 256>>>(Wp, Wk);

    const int smem_bytes = (TS * ND + DCHUNK * NOUT + TS * NKHP) * (int)sizeof(float); // 106496
    cudaFuncSetAttribute(sdca_kernel, cudaFuncAttributeMaxDynamicSharedMemorySize, smem_bytes);
    dim3 grid(NB * (NS / TS));  // 512 blocks
    sdca_kernel<<<grid, NTHREADS, smem_bytes>>>(q, ks, v, bk, bp, out);
}

// round 3
// speedup vs baseline: 1.5887x; 1.0679x over previous
#include <cuda_runtime.h>
#include <cuda_bf16.h>
#include <cstddef>

// Problem constants
#define NB    16
#define NS    1024
#define ND    384      // H * HD
#define NH    6
#define NHD   64
#define NK    9
#define NKH   54       // K * H
#define NKHP  64       // padded logits width
#define NOUT  384
#define NPAD  4        // K/2

// Tiling
#define TS       32    // seq rows per block
#define NTHREADS 256
#define KCHUNK   16    // K-chunk of WkT staged in smem (P2)
#define VROWS    24    // v rows staged per conv half-pass
#define ASTRIDE  392   // padded bf16 row stride for A fragments (bank-conflict-free)

// P5 mma tiling: 24 k-steps (k16), warp = 16 rows x 96 cols (12 n8 tiles)
#define NKSTEP   24
#define NJT      12

// B fragment pack: [kstep(24)][colblock(4)][lane(32)][tile(12)][4 regs: bh0,bh1,bl0,bl1]
#define BPACK_WORDS (NKSTEP * 4 * 32 * NJT * 4)   // 147456

// ---------------- packed f32x2 helpers (P2 logits GEMM) ----------------
__device__ __forceinline__ unsigned long long pack2(float x, float y) {
    unsigned long long r;
    asm("mov.b64 %0, {%1, %2};" : "=l"(r) : "f"(x), "f"(y));
    return r;
}
__device__ __forceinline__ void unpack2(unsigned long long v, float& x, float& y) {
    asm("mov.b64 {%0, %1}, %2;" : "=f"(x), "=f"(y) : "l"(v));
}
__device__ __forceinline__ void ffma2(unsigned long long& d,
                                      unsigned long long a,
                                      unsigned long long b) {
    asm("fma.rn.f32x2 %0, %1, %2, %0;" : "+l"(d) : "l"(a), "l"(b));
}

// ---------------- bf16 mma helper ----------------
__device__ __forceinline__ void mma_bf16(float* c,
                                         unsigned a0, unsigned a1,
                                         unsigned a2, unsigned a3,
                                         unsigned b0, unsigned b1) {
    asm volatile(
        "mma.sync.aligned.m16n8k16.row.col.f32.bf16.bf16.f32 "
        "{%0,%1,%2,%3}, {%4,%5,%6,%7}, {%8,%9}, {%0,%1,%2,%3};\n"
        : "+f"(c[0]), "+f"(c[1]), "+f"(c[2]), "+f"(c[3])
        : "r"(a0), "r"(a1), "r"(a2), "r"(a3), "r"(b0), "r"(b1));
}

// Device-global scratch (no allocation allowed)
__device__ float        g_WkT[ND * NKHP];       // WkT[d][o], padded 54->64
__device__ unsigned int g_Bpack[BPACK_WORDS];   // fragment-packed Wp hi/lo

__global__ void prep_kernel(const float* __restrict__ Wp,
                            const float* __restrict__ Wk) {
    int i = blockIdx.x * blockDim.x + threadIdx.x;
    if (i < ND * NKHP) {
        int d = i / NKHP, o = i % NKHP;
        g_WkT[i] = (o < NKH) ? Wk[o * ND + d] : 0.0f;
    }
    if (i < BPACK_WORDS) {
        int w  = i % (NJT * 4);
        int j  = w >> 2;          // tile 0..11
        int p  = w & 3;           // 0=bh0 1=bh1 2=bl0 3=bl1
        int l  = (i / (NJT * 4)) & 31;
        int cb = (i / (NJT * 4 * 32)) & 3;
        int t  =  i / (NJT * 4 * 32 * 4);
        int o  = cb * 96 + j * 8 + (l >> 2);
        int k0 = t * 16 + (l & 3) * 2 + ((p & 1) ? 8 : 0);
        float x = Wp[o * ND + k0];
        float y = Wp[o * ND + k0 + 1];
        unsigned r;
        if (p < 2) {
            __nv_bfloat162 h = __floats2bfloat162_rn(x, y);
            r = *reinterpret_cast<unsigned*>(&h);
        } else {
            float xh = __bfloat162float(__float2bfloat16_rn(x));
            float yh = __bfloat162float(__float2bfloat16_rn(y));
            __nv_bfloat162 h = __floats2bfloat162_rn(x - xh, y - yh);
            r = *reinterpret_cast<unsigned*>(&h);
        }
        g_Bpack[i] = r;
    }
}

// smem layout (floats):
//   region0 [0, 12544): union of
//       sA  fp32 [32 x 384]                (P1 q*ks, P2 input)
//       sAh/sAl bf16 [2 x 32 x 392]        (P4 output, P5 A operand)
//   sV  [12544, 21760): 24 x 384           (P4 v staging)
//   sKW [21760, 22784): 16 x 64            (P2 WkT chunk)
//   sL  [22784, 24832): 32 x 64            (logits / softmax)
#define SMEM_FLOATS 24832

__global__ __launch_bounds__(NTHREADS, 2) void sdca_kernel(
    const float* __restrict__ q,
    const float* __restrict__ ks,
    const float* __restrict__ v,
    const float* __restrict__ bk,
    const float* __restrict__ bp,
    float* __restrict__ out)
{
    extern __shared__ float smem[];
    float* sA  = smem;                  // region0 as fp32
    float* sV  = smem + 12544;
    float* sKW = smem + 21760;
    float* sL  = smem + 22784;
    __nv_bfloat16* sAh = (__nv_bfloat16*)smem;                 // 32 x ASTRIDE
    __nv_bfloat16* sAl = sAh + TS * ASTRIDE;

    const int tid  = threadIdx.x;
    const int lane = tid & 31;
    const int wrp  = tid >> 5;
    const int b    = blockIdx.x / (NS / TS);
    const int s0   = (blockIdx.x % (NS / TS)) * TS;

    // ---------- P1: sA = q * ks (vectorized) ----------
    {
        const float4* qb = (const float4*)(q  + ((size_t)b * NS + s0) * ND);
        const float4* kb = (const float4*)(ks + ((size_t)b * NS + s0) * ND);
        float4* a4 = (float4*)sA;
        #pragma unroll
        for (int i = tid; i < TS * ND / 4; i += NTHREADS) {
            float4 qq = qb[i], kk = kb[i];
            a4[i] = make_float4(qq.x * kk.x, qq.y * kk.y, qq.z * kk.z, qq.w * kk.w);
        }
    }
    __syncthreads();

    // ---------- P2: logits[32 x 64] = sA @ WkT  (f32x2 register GEMM) ----------
    {
        const int tx = lane, ty = wrp;
        unsigned long long acc2[4] = {0ull, 0ull, 0ull, 0ull};
        for (int d0 = 0; d0 < ND; d0 += KCHUNK) {
            ((float4*)sKW)[tid] = ((const float4*)(g_WkT + d0 * NKHP))[tid];
            __syncthreads();
            #pragma unroll
            for (int dd = 0; dd < KCHUNK; dd++) {
                unsigned long long wv =
                    *(const unsigned long long*)&sKW[dd * NKHP + 2 * tx];
                #pragma unroll
                for (int rr = 0; rr < 4; rr++) {
                    float a = sA[(ty * 4 + rr) * ND + d0 + dd];
                    ffma2(acc2[rr], pack2(a, a), wv);
                }
            }
            __syncthreads();
        }
        int o0 = 2 * tx, o1 = 2 * tx + 1;
        float bk0 = (o0 < NKH) ? bk[o0] : 0.f;
        float bk1 = (o1 < NKH) ? bk[o1] : 0.f;
        #pragma unroll
        for (int rr = 0; rr < 4; rr++) {
            float x, y; unpack2(acc2[rr], x, y);
            int r = ty * 4 + rr;
            sL[r * NKHP + o0] = x + bk0;
            sL[r * NKHP + o1] = y + bk1;
        }
    }
    __syncthreads();

    // ---------- P3: softmax over K=9 taps per (row, head) ----------
    if (tid < TS * NH) {
        int r = tid / NH, h = tid % NH;
        float* p = sL + r * NKHP + h * NK;
        float m = p[0];
        #pragma unroll
        for (int k = 1; k < NK; k++) m = fmaxf(m, p[k]);
        float e[NK], ssum = 0.f;
        #pragma unroll
        for (int k = 0; k < NK; k++) { e[k] = __expf(p[k] - m); ssum += e[k]; }
        float inv = 1.0f / ssum;
        #pragma unroll
        for (int k = 0; k < NK; k++) p[k] = e[k] * inv;
    }
    __syncthreads();

    // ---------- P4: dynamic conv; write hi/lo bf16 split into region0 ----------
    {
        const float* vb = v + (size_t)b * NS * ND;
        #pragma unroll
        for (int half = 0; half < 2; half++) {
            int gbase = s0 - NPAD + 16 * half;
            float4* sv4 = (float4*)sV;
            for (int i = tid; i < VROWS * ND / 4; i += NTHREADS) {
                int rr = i / (ND / 4);
                int gr = gbase + rr;
                float4 val = make_float4(0.f, 0.f, 0.f, 0.f);
                if (gr >= 0 && gr < NS)
                    val = ((const float4*)(vb + (size_t)gr * ND))[i % (ND / 4)];
                sv4[i] = val;
            }
            __syncthreads();

            for (int i = tid; i < 16 * ND; i += NTHREADS) {
                int rl = i / ND;            // 0..15
                int c  = i % ND;
                int r  = 16 * half + rl;    // block-local row
                const float* dkp = sL + r * NKHP + (c / NHD) * NK;
                float acc = 0.f;
                #pragma unroll
                for (int k = 0; k < NK; k++)
                    acc = fmaf(dkp[k], sV[(rl + k) * ND + c], acc);
                __nv_bfloat16 ah = __float2bfloat16_rn(acc);
                __nv_bfloat16 al = __float2bfloat16_rn(acc - __bfloat162float(ah));
                sAh[r * ASTRIDE + c] = ah;
                sAl[r * ASTRIDE + c] = al;
            }
            __syncthreads();
        }
    }

    // ---------- P5: out[32 x 384] = A @ Wp^T + bp  via bf16 3-split mma ----------
    // warp: rows rb..rb+15 (rb = 16*(wrp&1)), cols cb*96..+95 (cb = wrp>>1)
    {
        const int rb = (wrp & 1) * 16;
        const int cb = wrp >> 1;
        const int r0 = rb + (lane >> 2);
        const int kc = (lane & 3) * 2;

        float acc[NJT][4];
        #pragma unroll
        for (int j = 0; j < NJT; j++)
            #pragma unroll
            for (int p = 0; p < 4; p++) acc[j][p] = 0.f;

        for (int t = 0; t < NKSTEP; t++) {
            const uint4* bsrc =
                (const uint4*)(g_Bpack + ((size_t)((t * 4 + cb) * 32 + lane)) * (NJT * 4));
            uint4 B[NJT];
            #pragma unroll
            for (int j = 0; j < NJT; j++) B[j] = bsrc[j];

            int k0 = t * 16 + kc;
            unsigned ah0 = *(const unsigned*)(sAh + (size_t)r0 * ASTRIDE + k0);
            unsigned ah1 = *(const unsigned*)(sAh + (size_t)(r0 + 8) * ASTRIDE + k0);
            unsigned ah2 = *(const unsigned*)(sAh + (size_t)r0 * ASTRIDE + k0 + 8);
            unsigned ah3 = *(const unsigned*)(sAh + (size_t)(r0 + 8) * ASTRIDE + k0 + 8);
            unsigned al0 = *(const unsigned*)(sAl + (size_t)r0 * ASTRIDE + k0);
            unsigned al1 = *(const unsigned*)(sAl + (size_t)(r0 + 8) * ASTRIDE + k0);
            unsigned al2 = *(const unsigned*)(sAl + (size_t)r0 * ASTRIDE + k0 + 8);
            unsigned al3 = *(const unsigned*)(sAl + (size_t)(r0 + 8) * ASTRIDE + k0 + 8);

            #pragma unroll
            for (int j = 0; j < NJT; j++) {
                mma_bf16(acc[j], ah0, ah1, ah2, ah3, B[j].x, B[j].y);  // ah*bh
                mma_bf16(acc[j], al0, al1, al2, al3, B[j].x, B[j].y);  // al*bh
                mma_bf16(acc[j], ah0, ah1, ah2, ah3, B[j].z, B[j].w);  // ah*bl
            }
        }

        // epilogue: bias + store (float2 per acc pair)
        float* ob = out + ((size_t)b * NS + s0) * NOUT;
        const int col0 = cb * 96;
        #pragma unroll
        for (int j = 0; j < NJT; j++) {
            int c = col0 + j * 8 + kc;
            float2 bb = *(const float2*)&bp[c];
            float2 lo = make_float2(acc[j][0] + bb.x, acc[j][1] + bb.y);
            float2 hi = make_float2(acc[j][2] + bb.x, acc[j][3] + bb.y);
            *(float2*)&ob[(size_t)r0 * NOUT + c]       = lo;
            *(float2*)&ob[(size_t)(r0 + 8) * NOUT + c] = hi;
        }
    }
}

extern "C" void kernel_launch(void* const* d_in, const int* in_sizes, int n_in,
                              void* d_out, int out_size) {
    const float* q  = (const float*)d_in[0];
    const float* ks = (const float*)d_in[1];
    const float* v  = (const float*)d_in[2];
    const float* Wk = (const float*)d_in[3];
    const float* bk = (const float*)d_in[4];
    const float* Wp = (const float*)d_in[5];
    const float* bp = (const float*)d_in[6];
    float* out = (float*)d_out;

    (void)in_sizes; (void)n_in; (void)out_size;

    prep_kernel<<<(BPACK_WORDS + 255) / 256, 256>>>(Wp, Wk);

    const int smem_bytes = SMEM_FLOATS * (int)sizeof(float);  // 99328
    cudaFuncSetAttribute(sdca_kernel, cudaFuncAttributeMaxDynamicSharedMemorySize, smem_bytes);
    dim3 grid(NB * (NS / TS));  // 512 blocks
    sdca_kernel<<<grid, NTHREADS, smem_bytes>>>(q, ks, v, bk, bp, out);
}

// round 4
// speedup vs baseline: 1.9862x; 1.2502x over previous
#include <cuda_runtime.h>
#include <cuda_bf16.h>
#include <cstddef>
#include <cstdint>

// Problem constants
#define NB    16
#define NS    1024
#define ND    384      // H * HD
#define NH    6
#define NHD   64
#define NK    9
#define NKH   54       // K * H
#define NKHP  64       // padded logits width
#define NOUT  384
#define NPAD  4        // K/2

// K1 tiling
#define TS       32
#define K1THREADS 256
#define KCHUNK   16
#define VROWS    24

// K2 tiling: block 64 rows x 384 cols, 512 threads, warp 32x48
#define K2THREADS 512
#define NKSTEP   24
#define NJT      6     // n8 tiles per warp
#define NCB      8     // col blocks of 48

// B pack: [t(24)][cb(8)][lane(32)][j(6)][p(4)]  (p: bh0,bh1,bl0,bl1)
#define BPACK_WORDS (NKSTEP * NCB * 32 * NJT * 4)   // 147456

// ---------------- packed f32x2 helpers ----------------
__device__ __forceinline__ unsigned long long pack2(float x, float y) {
    unsigned long long r;
    asm("mov.b64 %0, {%1, %2};" : "=l"(r) : "f"(x), "f"(y));
    return r;
}
__device__ __forceinline__ void unpack2(unsigned long long v, float& x, float& y) {
    asm("mov.b64 {%0, %1}, %2;" : "=f"(x), "=f"(y) : "l"(v));
}
__device__ __forceinline__ void ffma2(unsigned long long& d,
                                      unsigned long long a,
                                      unsigned long long b) {
    asm("fma.rn.f32x2 %0, %1, %2, %0;" : "+l"(d) : "l"(a), "l"(b));
}

// ---------------- bf16 mma ----------------
__device__ __forceinline__ void mma_bf16(float* c,
                                         unsigned a0, unsigned a1,
                                         unsigned a2, unsigned a3,
                                         unsigned b0, unsigned b1) {
    asm volatile(
        "mma.sync.aligned.m16n8k16.row.col.f32.bf16.bf16.f32 "
        "{%0,%1,%2,%3}, {%4,%5,%6,%7}, {%8,%9}, {%0,%1,%2,%3};\n"
        : "+f"(c[0]), "+f"(c[1]), "+f"(c[2]), "+f"(c[3])
        : "r"(a0), "r"(a1), "r"(a2), "r"(a3), "r"(b0), "r"(b1));
}

// Device-global scratch
__device__ float        g_WkT[ND * NKHP];             // WkT[d][o], padded
__device__ unsigned int g_Bpack[BPACK_WORDS];         // Wp fragment pack
__device__ unsigned int g_A32[(size_t)NB * NS * ND];  // conv out, interleaved (hi,lo) bf16x2 words

__global__ void prep_kernel(const float* __restrict__ Wp,
                            const float* __restrict__ Wk) {
    int i = blockIdx.x * blockDim.x + threadIdx.x;
    if (i < ND * NKHP) {
        int d = i / NKHP, o = i % NKHP;
        g_WkT[i] = (o < NKH) ? Wk[o * ND + d] : 0.0f;
    }
    if (i < BPACK_WORDS) {
        int p  = i & 3;
        int j  = (i >> 2) % NJT;
        int l  = (i / (NJT * 4)) & 31;
        int cb = (i / (NJT * 4 * 32)) % NCB;
        int t  =  i / (NJT * 4 * 32 * NCB);
        int o  = cb * 48 + j * 8 + (l >> 2);
        int k0 = t * 16 + (l & 3) * 2 + ((p & 1) ? 8 : 0);
        float x = Wp[o * ND + k0];
        float y = Wp[o * ND + k0 + 1];
        unsigned r;
        if (p < 2) {
            __nv_bfloat162 h = __floats2bfloat162_rn(x, y);
            r = *reinterpret_cast<unsigned*>(&h);
        } else {
            float xh = __bfloat162float(__float2bfloat16_rn(x));
            float yh = __bfloat162float(__float2bfloat16_rn(y));
            __nv_bfloat162 h = __floats2bfloat162_rn(x - xh, y - yh);
            r = *reinterpret_cast<unsigned*>(&h);
        }
        g_Bpack[i] = r;
    }
}

// ============================================================================
// K1: q*ks -> logits -> softmax -> dynamic conv -> bf16 hi/lo planes (global)
// smem floats: sA [0,12288)  sV [12288,21504)  sKW [21504,22528)  sL [22528,24576)
// ============================================================================
#define K1_SMEM_FLOATS 24576

__global__ __launch_bounds__(K1THREADS) void k1_kernel(
    const float* __restrict__ q,
    const float* __restrict__ ks,
    const float* __restrict__ v,
    const float* __restrict__ bk)
{
    extern __shared__ float smem[];
    float* sA  = smem;
    float* sV  = smem + 12288;
    float* sKW = smem + 21504;
    float* sL  = smem + 22528;

    const int tid  = threadIdx.x;
    const int lane = tid & 31;
    const int wrp  = tid >> 5;
    const int b    = blockIdx.x / (NS / TS);
    const int s0   = (blockIdx.x % (NS / TS)) * TS;

    // ---- P1: sA = q * ks ----
    {
        const float4* qb = (const float4*)(q  + ((size_t)b * NS + s0) * ND);
        const float4* kb = (const float4*)(ks + ((size_t)b * NS + s0) * ND);
        float4* a4 = (float4*)sA;
        #pragma unroll
        for (int i = tid; i < TS * ND / 4; i += K1THREADS) {
            float4 qq = qb[i], kk = kb[i];
            a4[i] = make_float4(qq.x * kk.x, qq.y * kk.y, qq.z * kk.z, qq.w * kk.w);
        }
    }
    __syncthreads();

    // ---- P2: logits[32 x 64] = sA @ WkT (f32x2, float4 A broadcasts) ----
    {
        const int tx = lane, ty = wrp;
        unsigned long long acc2[4] = {0ull, 0ull, 0ull, 0ull};
        for (int d0 = 0; d0 < ND; d0 += KCHUNK) {
            ((float4*)sKW)[tid] = ((const float4*)(g_WkT + d0 * NKHP))[tid];
            __syncthreads();
            #pragma unroll
            for (int dd4 = 0; dd4 < KCHUNK / 4; dd4++) {
                float4 av[4];
                #pragma unroll
                for (int rr = 0; rr < 4; rr++)
                    av[rr] = *(const float4*)&sA[(ty * 4 + rr) * ND + d0 + dd4 * 4];
                #pragma unroll
                for (int e = 0; e < 4; e++) {
                    unsigned long long wv =
                        *(const unsigned long long*)&sKW[(dd4 * 4 + e) * NKHP + 2 * tx];
                    float a0 = (e == 0) ? av[0].x : (e == 1) ? av[0].y : (e == 2) ? av[0].z : av[0].w;
                    float a1 = (e == 0) ? av[1].x : (e == 1) ? av[1].y : (e == 2) ? av[1].z : av[1].w;
                    float a2 = (e == 0) ? av[2].x : (e == 1) ? av[2].y : (e == 2) ? av[2].z : av[2].w;
                    float a3 = (e == 0) ? av[3].x : (e == 1) ? av[3].y : (e == 2) ? av[3].z : av[3].w;
                    ffma2(acc2[0], pack2(a0, a0), wv);
                    ffma2(acc2[1], pack2(a1, a1), wv);
                    ffma2(acc2[2], pack2(a2, a2), wv);
                    ffma2(acc2[3], pack2(a3, a3), wv);
                }
            }
            __syncthreads();
        }
        int o0 = 2 * tx, o1 = 2 * tx + 1;
        float bk0 = (o0 < NKH) ? bk[o0] : 0.f;
        float bk1 = (o1 < NKH) ? bk[o1] : 0.f;
        #pragma unroll
        for (int rr = 0; rr < 4; rr++) {
            float x, y; unpack2(acc2[rr], x, y);
            int r = ty * 4 + rr;
            sL[r * NKHP + o0] = x + bk0;
            sL[r * NKHP + o1] = y + bk1;
        }
    }
    __syncthreads();

    // ---- P3: softmax over K=9 taps per (row, head) ----
    if (tid < TS * NH) {
        int r = tid / NH, h = tid % NH;
        float* p = sL + r * NKHP + h * NK;
        float m = p[0];
        #pragma unroll
        for (int k = 1; k < NK; k++) m = fmaxf(m, p[k]);
        float e[NK], ssum = 0.f;
        #pragma unroll
        for (int k = 0; k < NK; k++) { e[k] = __expf(p[k] - m); ssum += e[k]; }
        float inv = 1.0f / ssum;
        #pragma unroll
        for (int k = 0; k < NK; k++) p[k] = e[k] * inv;
    }
    __syncthreads();

    // ---- P4: conv on column pairs; write interleaved (hi,lo) bf16x2 words ----
    {
        const float* vb = v + (size_t)b * NS * ND;
        #pragma unroll
        for (int half = 0; half < 2; half++) {
            int gbase = s0 - NPAD + 16 * half;
            float4* sv4 = (float4*)sV;
            for (int i = tid; i < VROWS * ND / 4; i += K1THREADS) {
                int rr = i / (ND / 4);
                int gr = gbase + rr;
                float4 val = make_float4(0.f, 0.f, 0.f, 0.f);
                if (gr >= 0 && gr < NS)
                    val = ((const float4*)(vb + (size_t)gr * ND))[i % (ND / 4)];
                sv4[i] = val;
            }
            __syncthreads();

            // 16 rows x 192 column-pairs
            for (int i = tid; i < 16 * (ND / 2); i += K1THREADS) {
                int rl = i / (ND / 2);
                int pi = i % (ND / 2);
                int c0 = 2 * pi;
                int r  = 16 * half + rl;
                const float* dkp = sL + r * NKHP + (c0 >> 6) * NK;
                float acc0 = 0.f, acc1 = 0.f;
                #pragma unroll
                for (int k = 0; k < NK; k++) {
                    float2 vv = *(const float2*)&sV[(rl + k) * ND + c0];
                    float dk = dkp[k];
                    acc0 = fmaf(dk, vv.x, acc0);
                    acc1 = fmaf(dk, vv.y, acc1);
                }
                // bf16 hi/lo split, interleaved pack
                __nv_bfloat162 hi = __floats2bfloat162_rn(acc0, acc1);
                float h0 = __bfloat162float(__low2bfloat16(hi));
                float h1 = __bfloat162float(__high2bfloat16(hi));
                __nv_bfloat162 lo = __floats2bfloat162_rn(acc0 - h0, acc1 - h1);
                uint2 w;
                w.x = *reinterpret_cast<unsigned*>(&hi);
                w.y = *reinterpret_cast<unsigned*>(&lo);
                size_t row = (size_t)b * NS + s0 + r;
                *(uint2*)&g_A32[row * ND + c0] = w;
            }
            __syncthreads();
        }
    }
}

// ============================================================================
// K2: out[16384 x 384] = A @ Wp^T + bp  (bf16 3-split mma, no smem/barriers)
// block = 64 rows x 384 cols, 512 threads; warp = 32 rows x 48 cols
// ============================================================================
__global__ __launch_bounds__(K2THREADS) void k2_kernel(
    const float* __restrict__ bp,
    float* __restrict__ out)
{
    const int tid    = threadIdx.x;
    const int lane   = tid & 31;
    const int wrp    = tid >> 5;
    const int warp_m = wrp & 1;       // 0..1
    const int warp_n = wrp >> 1;      // 0..7
    const int rbase  = blockIdx.x * 64 + warp_m * 32;
    const int rq     = lane >> 2;     // 0..7
    const int kc     = (lane & 3) * 2;

    float acc[2][NJT][4];
    #pragma unroll
    for (int mt = 0; mt < 2; mt++)
        #pragma unroll
        for (int j = 0; j < NJT; j++)
            #pragma unroll
            for (int p = 0; p < 4; p++) acc[mt][j][p] = 0.f;

    const unsigned* A = g_A32;
    for (int t = 0; t < NKSTEP; t++) {
        const int k0 = t * 16;
        // A fragments: (hi, lo) pairs via single LDG.64 each
        uint2 a[2][4];   // [mt][pos]: pos0=(r,kc) pos1=(r+8,kc) pos2=(r,kc+8) pos3=(r+8,kc+8)
        #pragma unroll
        for (int mt = 0; mt < 2; mt++) {
            size_t R = (size_t)(rbase + mt * 16 + rq);
            a[mt][0] = *(const uint2*)(A + R * ND + k0 + kc);
            a[mt][1] = *(const uint2*)(A + (R + 8) * ND + k0 + kc);
            a[mt][2] = *(const uint2*)(A + R * ND + k0 + kc + 8);
            a[mt][3] = *(const uint2*)(A + (R + 8) * ND + k0 + kc + 8);
        }
        const uint4* bptr =
            (const uint4*)(g_Bpack + ((size_t)((t * NCB + warp_n) * 32 + lane)) * (NJT * 4));
        #pragma unroll
        for (int j = 0; j < NJT; j++) {
            uint4 B = bptr[j];
            #pragma unroll
            for (int mt = 0; mt < 2; mt++) {
                mma_bf16(acc[mt][j], a[mt][0].x, a[mt][1].x, a[mt][2].x, a[mt][3].x, B.x, B.y); // ah*bh
                mma_bf16(acc[mt][j], a[mt][0].y, a[mt][1].y, a[mt][2].y, a[mt][3].y, B.x, B.y); // al*bh
                mma_bf16(acc[mt][j], a[mt][0].x, a[mt][1].x, a[mt][2].x, a[mt][3].x, B.z, B.w); // ah*bl
            }
        }
    }

    // epilogue
    const int nbase = warp_n * 48;
    #pragma unroll
    for (int j = 0; j < NJT; j++) {
        int c = nbase + j * 8 + kc;
        float2 bb = *(const float2*)&bp[c];
        #pragma unroll
        for (int mt = 0; mt < 2; mt++) {
            size_t R = (size_t)(rbase + mt * 16 + rq);
            float2 lo = make_float2(acc[mt][j][0] + bb.x, acc[mt][j][1] + bb.y);
            float2 hi = make_float2(acc[mt][j][2] + bb.x, acc[mt][j][3] + bb.y);
            *(float2*)&out[R * NOUT + c]       = lo;
            *(float2*)&out[(R + 8) * NOUT + c] = hi;
        }
    }
}

extern "C" void kernel_launch(void* const* d_in, const int* in_sizes, int n_in,
                              void* d_out, int out_size) {
    const float* q  = (const float*)d_in[0];
    const float* ks = (const float*)d_in[1];
    const float* v  = (const float*)d_in[2];
    const float* Wk = (const float*)d_in[3];
    const float* bk = (const float*)d_in[4];
    const float* Wp = (const float*)d_in[5];
    const float* bp = (const float*)d_in[6];
    float* out = (float*)d_out;

    (void)in_sizes; (void)n_in; (void)out_size;

    prep_kernel<<<(BPACK_WORDS + 255) / 256, 256>>>(Wp, Wk);

    const int k1_smem = K1_SMEM_FLOATS * (int)sizeof(float);  // 98304
    cudaFuncSetAttribute(k1_kernel, cudaFuncAttributeMaxDynamicSharedMemorySize, k1_smem);
    k1_kernel<<<NB * (NS / TS), K1THREADS, k1_smem>>>(q, ks, v, bk);

    k2_kernel<<<(NB * NS) / 64, K2THREADS>>>(bp, out);
}

// round 5
// speedup vs baseline: 2.1669x; 1.0910x over previous
#include <cuda_runtime.h>
#include <cuda_bf16.h>
#include <cstddef>
#include <cstdint>

// Problem constants
#define NB    16
#define NS    1024
#define ND    384      // H * HD
#define NH    6
#define NHD   64
#define NK    9
#define NKH   54       // K * H
#define NKHP  64       // padded logits width
#define NOUT  384
#define NPAD  4        // K/2

// K1 tiling
#define TS       32
#define K1THREADS 256
#define VROWS    24
#define AST      392   // bf16 plane row stride (halfs), conflict-free frag LDS

// K2 tiling: block 64 rows x 384 cols, 512 threads, warp 32x48
#define K2THREADS 512
#define NKSTEP   24
#define NJT      6     // n8 tiles per warp (K2)
#define NCB      8     // col blocks of 48 (K2)

// Wp B pack: [t(24)][cb(8)][lane(32)][j(6)][p(4)]
#define BPACK_WORDS (NKSTEP * NCB * 32 * NJT * 4)      // 147456
// Wk B pack: [t(24)][lane(32)][j(8)][p(4)]
#define WKPACK_WORDS (NKSTEP * 32 * 8 * 4)             // 24576

// ---------------- bf16 mma ----------------
__device__ __forceinline__ void mma_bf16(float* c,
                                         unsigned a0, unsigned a1,
                                         unsigned a2, unsigned a3,
                                         unsigned b0, unsigned b1) {
    asm volatile(
        "mma.sync.aligned.m16n8k16.row.col.f32.bf16.bf16.f32 "
        "{%0,%1,%2,%3}, {%4,%5,%6,%7}, {%8,%9}, {%0,%1,%2,%3};\n"
        : "+f"(c[0]), "+f"(c[1]), "+f"(c[2]), "+f"(c[3])
        : "r"(a0), "r"(a1), "r"(a2), "r"(a3), "r"(b0), "r"(b1));
}

// Device-global scratch
__device__ unsigned int g_Bpack[BPACK_WORDS];          // Wp fragment pack (hi/lo)
__device__ unsigned int g_WkPack[WKPACK_WORDS];        // Wk fragment pack (hi/lo)
__device__ unsigned int g_A32[(size_t)NB * NS * ND];   // conv out, interleaved (hi,lo) bf16x2

__device__ __forceinline__ unsigned split_pack(float x, float y, int p) {
    // p<2 -> hi bf16x2 of (x,y); p>=2 -> lo residual bf16x2
    if (p < 2) {
        __nv_bfloat162 h = __floats2bfloat162_rn(x, y);
        return *reinterpret_cast<unsigned*>(&h);
    } else {
        float xh = __bfloat162float(__float2bfloat16_rn(x));
        float yh = __bfloat162float(__float2bfloat16_rn(y));
        __nv_bfloat162 h = __floats2bfloat162_rn(x - xh, y - yh);
        return *reinterpret_cast<unsigned*>(&h);
    }
}

__global__ void prep_kernel(const float* __restrict__ Wp,
                            const float* __restrict__ Wk) {
    int i = blockIdx.x * blockDim.x + threadIdx.x;
    if (i < BPACK_WORDS) {
        int p  = i & 3;
        int j  = (i >> 2) % NJT;
        int l  = (i / (NJT * 4)) & 31;
        int cb = (i / (NJT * 4 * 32)) % NCB;
        int t  =  i / (NJT * 4 * 32 * NCB);
        int o  = cb * 48 + j * 8 + (l >> 2);
        int k0 = t * 16 + (l & 3) * 2 + ((p & 1) ? 8 : 0);
        g_Bpack[i] = split_pack(Wp[o * ND + k0], Wp[o * ND + k0 + 1], p);
    }
    if (i < WKPACK_WORDS) {
        int p  = i & 3;
        int j  = (i >> 2) & 7;
        int l  = (i >> 5) & 31;
        int t  =  i >> 10;
        int o  = j * 8 + (l >> 2);
        int k0 = t * 16 + (l & 3) * 2 + ((p & 1) ? 8 : 0);
        float x = (o < NKH) ? Wk[o * ND + k0]     : 0.f;
        float y = (o < NKH) ? Wk[o * ND + k0 + 1] : 0.f;
        g_WkPack[i] = split_pack(x, y, p);
    }
}

// ============================================================================
// K1: q*ks (bf16 split planes) -> mma logits -> softmax -> conv -> g_A32
// smem (floats):
//   sAh [0, 6272)        32 x 392 halfs
//   sAl [6272, 12544)
//   sV  [12544, 21760)   24 x 384 fp32
//   sL  [21760, 23808)   32 x 64  fp32
// ============================================================================
#define K1_SMEM_FLOATS 23808

__global__ __launch_bounds__(K1THREADS) void k1_kernel(
    const float* __restrict__ q,
    const float* __restrict__ ks,
    const float* __restrict__ v,
    const float* __restrict__ bk)
{
    extern __shared__ float smem[];
    __nv_bfloat16* sAh = (__nv_bfloat16*)smem;           // 32 x AST halfs
    __nv_bfloat16* sAl = sAh + TS * AST;
    float* sV = smem + 12544;
    float* sL = smem + 21760;

    const int tid  = threadIdx.x;
    const int lane = tid & 31;
    const int wrp  = tid >> 5;
    const int b    = blockIdx.x / (NS / TS);
    const int s0   = (blockIdx.x % (NS / TS)) * TS;

    // ---- P1: sAh/sAl = bf16 split of q*ks ----
    {
        const float4* qb = (const float4*)(q  + ((size_t)b * NS + s0) * ND);
        const float4* kb = (const float4*)(ks + ((size_t)b * NS + s0) * ND);
        for (int i = tid; i < TS * (ND / 4); i += K1THREADS) {
            int r  = i / (ND / 4);
            int c4 = (i % (ND / 4)) * 4;
            float4 qq = qb[i], kk = kb[i];
            float p0 = qq.x * kk.x, p1 = qq.y * kk.y;
            float p2 = qq.z * kk.z, p3 = qq.w * kk.w;
            __nv_bfloat162 h01 = __floats2bfloat162_rn(p0, p1);
            __nv_bfloat162 h23 = __floats2bfloat162_rn(p2, p3);
            float h0 = __bfloat162float(__low2bfloat16(h01));
            float h1 = __bfloat162float(__high2bfloat16(h01));
            float h2 = __bfloat162float(__low2bfloat16(h23));
            float h3 = __bfloat162float(__high2bfloat16(h23));
            __nv_bfloat162 l01 = __floats2bfloat162_rn(p0 - h0, p1 - h1);
            __nv_bfloat162 l23 = __floats2bfloat162_rn(p2 - h2, p3 - h3);
            uint2 wh, wl;
            wh.x = *reinterpret_cast<unsigned*>(&h01);
            wh.y = *reinterpret_cast<unsigned*>(&h23);
            wl.x = *reinterpret_cast<unsigned*>(&l01);
            wl.y = *reinterpret_cast<unsigned*>(&l23);
            *(uint2*)&sAh[r * AST + c4] = wh;
            *(uint2*)&sAl[r * AST + c4] = wl;
        }
    }
    __syncthreads();

    // ---- P2: logits[32 x 64] via bf16 3-split mma; warp = n8 tile wrp ----
    {
        const int rq = lane >> 2;
        const int kc = (lane & 3) * 2;
        float acc[2][4];
        #pragma unroll
        for (int mt = 0; mt < 2; mt++)
            #pragma unroll
            for (int p = 0; p < 4; p++) acc[mt][p] = 0.f;

        for (int t = 0; t < NKSTEP; t++) {
            const int k0 = t * 16;
            uint4 B = *(const uint4*)(g_WkPack + (((size_t)(t * 32 + lane)) * 8 + wrp) * 4);
            #pragma unroll
            for (int mt = 0; mt < 2; mt++) {
                int r = mt * 16 + rq;
                unsigned ah0 = *(const unsigned*)(sAh + (size_t)r * AST + k0 + kc);
                unsigned ah1 = *(const unsigned*)(sAh + (size_t)(r + 8) * AST + k0 + kc);
                unsigned ah2 = *(const unsigned*)(sAh + (size_t)r * AST + k0 + kc + 8);
                unsigned ah3 = *(const unsigned*)(sAh + (size_t)(r + 8) * AST + k0 + kc + 8);
                unsigned al0 = *(const unsigned*)(sAl + (size_t)r * AST + k0 + kc);
                unsigned al1 = *(const unsigned*)(sAl + (size_t)(r + 8) * AST + k0 + kc);
                unsigned al2 = *(const unsigned*)(sAl + (size_t)r * AST + k0 + kc + 8);
                unsigned al3 = *(const unsigned*)(sAl + (size_t)(r + 8) * AST + k0 + kc + 8);
                mma_bf16(acc[mt], ah0, ah1, ah2, ah3, B.x, B.y);
                mma_bf16(acc[mt], al0, al1, al2, al3, B.x, B.y);
                mma_bf16(acc[mt], ah0, ah1, ah2, ah3, B.z, B.w);
            }
        }

        // write logits + bk into sL
        int oc = wrp * 8 + kc;
        float bk0 = (oc < NKH)     ? bk[oc]     : 0.f;
        float bk1 = (oc + 1 < NKH) ? bk[oc + 1] : 0.f;
        #pragma unroll
        for (int mt = 0; mt < 2; mt++) {
            int r = mt * 16 + rq;
            sL[r * NKHP + oc]           = acc[mt][0] + bk0;
            sL[r * NKHP + oc + 1]       = acc[mt][1] + bk1;
            sL[(r + 8) * NKHP + oc]     = acc[mt][2] + bk0;
            sL[(r + 8) * NKHP + oc + 1] = acc[mt][3] + bk1;
        }
    }
    __syncthreads();

    // ---- P3: softmax over K=9 taps per (row, head) ----
    if (tid < TS * NH) {
        int r = tid / NH, h = tid % NH;
        float* p = sL + r * NKHP + h * NK;
        float m = p[0];
        #pragma unroll
        for (int k = 1; k < NK; k++) m = fmaxf(m, p[k]);
        float e[NK], ssum = 0.f;
        #pragma unroll
        for (int k = 0; k < NK; k++) { e[k] = __expf(p[k] - m); ssum += e[k]; }
        float inv = 1.0f / ssum;
        #pragma unroll
        for (int k = 0; k < NK; k++) p[k] = e[k] * inv;
    }
    __syncthreads();

    // ---- P4: conv on column pairs; write interleaved (hi,lo) bf16x2 words ----
    {
        const float* vb = v + (size_t)b * NS * ND;
        #pragma unroll
        for (int half = 0; half < 2; half++) {
            int gbase = s0 - NPAD + 16 * half;
            float4* sv4 = (float4*)sV;
            for (int i = tid; i < VROWS * ND / 4; i += K1THREADS) {
                int rr = i / (ND / 4);
                int gr = gbase + rr;
                float4 val = make_float4(0.f, 0.f, 0.f, 0.f);
                if (gr >= 0 && gr < NS)
                    val = ((const float4*)(vb + (size_t)gr * ND))[i % (ND / 4)];
                sv4[i] = val;
            }
            __syncthreads();

            for (int i = tid; i < 16 * (ND / 2); i += K1THREADS) {
                int rl = i / (ND / 2);
                int pi = i % (ND / 2);
                int c0 = 2 * pi;
                int r  = 16 * half + rl;
                const float* dkp = sL + r * NKHP + (c0 >> 6) * NK;
                float acc0 = 0.f, acc1 = 0.f;
                #pragma unroll
                for (int k = 0; k < NK; k++) {
                    float2 vv = *(const float2*)&sV[(rl + k) * ND + c0];
                    float dk = dkp[k];
                    acc0 = fmaf(dk, vv.x, acc0);
                    acc1 = fmaf(dk, vv.y, acc1);
                }
                __nv_bfloat162 hi = __floats2bfloat162_rn(acc0, acc1);
                float h0 = __bfloat162float(__low2bfloat16(hi));
                float h1 = __bfloat162float(__high2bfloat16(hi));
                __nv_bfloat162 lo = __floats2bfloat162_rn(acc0 - h0, acc1 - h1);
                uint2 w;
                w.x = *reinterpret_cast<unsigned*>(&hi);
                w.y = *reinterpret_cast<unsigned*>(&lo);
                size_t row = (size_t)b * NS + s0 + r;
                *(uint2*)&g_A32[row * ND + c0] = w;
            }
            __syncthreads();
        }
    }
}

// ============================================================================
// K2: out[16384 x 384] = A @ Wp^T + bp  (bf16 3-split mma, no smem/barriers)
// ============================================================================
__global__ __launch_bounds__(K2THREADS) void k2_kernel(
    const float* __restrict__ bp,
    float* __restrict__ out)
{
    const int tid    = threadIdx.x;
    const int lane   = tid & 31;
    const int wrp    = tid >> 5;
    const int warp_m = wrp & 1;
    const int warp_n = wrp >> 1;
    const int rbase  = blockIdx.x * 64 + warp_m * 32;
    const int rq     = lane >> 2;
    const int kc     = (lane & 3) * 2;

    float acc[2][NJT][4];
    #pragma unroll
    for (int mt = 0; mt < 2; mt++)
        #pragma unroll
        for (int j = 0; j < NJT; j++)
            #pragma unroll
            for (int p = 0; p < 4; p++) acc[mt][j][p] = 0.f;

    const unsigned* A = g_A32;
    for (int t = 0; t < NKSTEP; t++) {
        const int k0 = t * 16;
        uint2 a[2][4];
        #pragma unroll
        for (int mt = 0; mt < 2; mt++) {
            size_t R = (size_t)(rbase + mt * 16 + rq);
            a[mt][0] = *(const uint2*)(A + R * ND + k0 + kc);
            a[mt][1] = *(const uint2*)(A + (R + 8) * ND + k0 + kc);
            a[mt][2] = *(const uint2*)(A + R * ND + k0 + kc + 8);
            a[mt][3] = *(const uint2*)(A + (R + 8) * ND + k0 + kc + 8);
        }
        const uint4* bptr =
            (const uint4*)(g_Bpack + ((size_t)((t * NCB + warp_n) * 32 + lane)) * (NJT * 4));
        #pragma unroll
        for (int j = 0; j < NJT; j++) {
            uint4 B = bptr[j];
            #pragma unroll
            for (int mt = 0; mt < 2; mt++) {
                mma_bf16(acc[mt][j], a[mt][0].x, a[mt][1].x, a[mt][2].x, a[mt][3].x, B.x, B.y);
                mma_bf16(acc[mt][j], a[mt][0].y, a[mt][1].y, a[mt][2].y, a[mt][3].y, B.x, B.y);
                mma_bf16(acc[mt][j], a[mt][0].x, a[mt][1].x, a[mt][2].x, a[mt][3].x, B.z, B.w);
            }
        }
    }

    const int nbase = warp_n * 48;
    #pragma unroll
    for (int j = 0; j < NJT; j++) {
        int c = nbase + j * 8 + kc;
        float2 bb = *(const float2*)&bp[c];
        #pragma unroll
        for (int mt = 0; mt < 2; mt++) {
            size_t R = (size_t)(rbase + mt * 16 + rq);
            float2 lo = make_float2(acc[mt][j][0] + bb.x, acc[mt][j][1] + bb.y);
            float2 hi = make_float2(acc[mt][j][2] + bb.x, acc[mt][j][3] + bb.y);
            *(float2*)&out[R * NOUT + c]       = lo;
            *(float2*)&out[(R + 8) * NOUT + c] = hi;
        }
    }
}

extern "C" void kernel_launch(void* const* d_in, const int* in_sizes, int n_in,
                              void* d_out, int out_size) {
    const float* q  = (const float*)d_in[0];
    const float* ks = (const float*)d_in[1];
    const float* v  = (const float*)d_in[2];
    const float* Wk = (const float*)d_in[3];
    const float* bk = (const float*)d_in[4];
    const float* Wp = (const float*)d_in[5];
    const float* bp = (const float*)d_in[6];
    float* out = (float*)d_out;

    (void)in_sizes; (void)n_in; (void)out_size;

    prep_kernel<<<(BPACK_WORDS + 255) / 256, 256>>>(Wp, Wk);

    const int k1_smem = K1_SMEM_FLOATS * (int)sizeof(float);  // 95232
    cudaFuncSetAttribute(k1_kernel, cudaFuncAttributeMaxDynamicSharedMemorySize, k1_smem);
    k1_kernel<<<NB * (NS / TS), K1THREADS, k1_smem>>>(q, ks, v, bk);

    k2_kernel<<<(NB * NS) / 64, K2THREADS>>>(bp, out);
}

// round 6
// speedup vs baseline: 3.0540x; 1.4094x over previous
#include <cuda_runtime.h>
#include <cuda_bf16.h>
#include <cstddef>
#include <cstdint>

// Problem constants
#define NB    16
#define NS    1024
#define ND    384      // H * HD
#define NH    6
#define NHD   64
#define NK    9
#define NKH   54       // K * H
#define NKHP  64       // padded logits width
#define NOUT  384
#define NPAD  4        // K/2

// Fused kernel tiling
#define TSR      64    // seq rows per block
#define NTH      512
#define AST      392   // bf16 plane row stride (halfs) — conflict-free frag LDS
#define VR       40    // v rows staged per conv half-pass (32 + 8 halo)

#define NKSTEP   24
#define NJT      6     // n8 tiles per warp in P5
#define NCB      8     // col blocks of 48

// Wp pack: [t(24)][cb(8)][lane(32)][j(6)][p(4)]
#define BPACK_WORDS (NKSTEP * NCB * 32 * NJT * 4)      // 147456
// Wk pack: [t(24)][lane(32)][j(8)][p(4)]
#define WKPACK_WORDS (NKSTEP * 32 * 8 * 4)             // 24576

// ---------------- bf16 mma ----------------
__device__ __forceinline__ void mma_bf16(float* c,
                                         unsigned a0, unsigned a1,
                                         unsigned a2, unsigned a3,
                                         unsigned b0, unsigned b1) {
    asm volatile(
        "mma.sync.aligned.m16n8k16.row.col.f32.bf16.bf16.f32 "
        "{%0,%1,%2,%3}, {%4,%5,%6,%7}, {%8,%9}, {%0,%1,%2,%3};\n"
        : "+f"(c[0]), "+f"(c[1]), "+f"(c[2]), "+f"(c[3])
        : "r"(a0), "r"(a1), "r"(a2), "r"(a3), "r"(b0), "r"(b1));
}

__device__ unsigned int g_Bpack[BPACK_WORDS];
__device__ unsigned int g_WkPack[WKPACK_WORDS];

__device__ __forceinline__ unsigned split_pack(float x, float y, int p) {
    if (p < 2) {
        __nv_bfloat162 h = __floats2bfloat162_rn(x, y);
        return *reinterpret_cast<unsigned*>(&h);
    } else {
        float xh = __bfloat162float(__float2bfloat16_rn(x));
        float yh = __bfloat162float(__float2bfloat16_rn(y));
        __nv_bfloat162 h = __floats2bfloat162_rn(x - xh, y - yh);
        return *reinterpret_cast<unsigned*>(&h);
    }
}

__global__ void prep_kernel(const float* __restrict__ Wp,
                            const float* __restrict__ Wk) {
    int i = blockIdx.x * blockDim.x + threadIdx.x;
    if (i < BPACK_WORDS) {
        int p  = i & 3;
        int j  = (i >> 2) % NJT;
        int l  = (i / (NJT * 4)) & 31;
        int cb = (i / (NJT * 4 * 32)) % NCB;
        int t  =  i / (NJT * 4 * 32 * NCB);
        int o  = cb * 48 + j * 8 + (l >> 2);
        int k0 = t * 16 + (l & 3) * 2 + ((p & 1) ? 8 : 0);
        g_Bpack[i] = split_pack(Wp[o * ND + k0], Wp[o * ND + k0 + 1], p);
    }
    if (i < WKPACK_WORDS) {
        int p  = i & 3;
        int j  = (i >> 2) & 7;
        int l  = (i >> 5) & 31;
        int t  =  i >> 10;
        int o  = j * 8 + (l >> 2);
        int k0 = t * 16 + (l & 3) * 2 + ((p & 1) ? 8 : 0);
        float x = (o < NKH) ? Wk[o * ND + k0]     : 0.f;
        float y = (o < NKH) ? Wk[o * ND + k0 + 1] : 0.f;
        g_WkPack[i] = split_pack(x, y, p);
    }
}

// ============================================================================
// Fused kernel: one block = (batch, 64 seq rows)
// smem (floats, total 44544 = 178176 B):
//   planes [0, 25088):       sAh/sAl 64 x 392 halfs each  (q*ks, then conv out)
//   sV     [25088, 40448):   40 x 384 fp32
//   sL     [40448, 44544):   64 x 64 fp32 logits/softmax
// ============================================================================
#define SMEM_FLOATS 44544

__global__ __launch_bounds__(NTH, 1) void sdca_fused(
    const float* __restrict__ q,
    const float* __restrict__ ks,
    const float* __restrict__ v,
    const float* __restrict__ bk,
    const float* __restrict__ bp,
    float* __restrict__ out)
{
    extern __shared__ float smem[];
    __nv_bfloat16* sAh = (__nv_bfloat16*)smem;           // 64 x AST halfs
    __nv_bfloat16* sAl = sAh + TSR * AST;
    float* sV = smem + 25088;
    float* sL = smem + 40448;

    const int tid  = threadIdx.x;
    const int lane = tid & 31;
    const int wrp  = tid >> 5;
    const int b    = blockIdx.x / (NS / TSR);
    const int s0   = (blockIdx.x % (NS / TSR)) * TSR;

    // ---- P1: planes = bf16 hi/lo split of q*ks ----
    {
        const float4* qb = (const float4*)(q  + ((size_t)b * NS + s0) * ND);
        const float4* kb = (const float4*)(ks + ((size_t)b * NS + s0) * ND);
        #pragma unroll
        for (int i = tid; i < TSR * (ND / 4); i += NTH) {
            int r  = i / (ND / 4);
            int c4 = (i % (ND / 4)) * 4;
            float4 qq = qb[i], kk = kb[i];
            float p0 = qq.x * kk.x, p1 = qq.y * kk.y;
            float p2 = qq.z * kk.z, p3 = qq.w * kk.w;
            __nv_bfloat162 h01 = __floats2bfloat162_rn(p0, p1);
            __nv_bfloat162 h23 = __floats2bfloat162_rn(p2, p3);
            float h0 = __bfloat162float(__low2bfloat16(h01));
            float h1 = __bfloat162float(__high2bfloat16(h01));
            float h2 = __bfloat162float(__low2bfloat16(h23));
            float h3 = __bfloat162float(__high2bfloat16(h23));
            __nv_bfloat162 l01 = __floats2bfloat162_rn(p0 - h0, p1 - h1);
            __nv_bfloat162 l23 = __floats2bfloat162_rn(p2 - h2, p3 - h3);
            uint2 wh, wl;
            wh.x = *reinterpret_cast<unsigned*>(&h01);
            wh.y = *reinterpret_cast<unsigned*>(&h23);
            wl.x = *reinterpret_cast<unsigned*>(&l01);
            wl.y = *reinterpret_cast<unsigned*>(&l23);
            *(uint2*)&sAh[r * AST + c4] = wh;
            *(uint2*)&sAl[r * AST + c4] = wl;
        }
    }
    __syncthreads();

    // ---- P2: logits[64 x 64] via bf16 3-split mma ----
    // warp: wm = wrp&1 (row half), wn = wrp>>1 (n8 tile)
    {
        const int wm = wrp & 1;
        const int wn = wrp >> 1;
        const int rq = lane >> 2;
        const int kc = (lane & 3) * 2;
        float acc[2][4];
        #pragma unroll
        for (int mt = 0; mt < 2; mt++)
            #pragma unroll
            for (int p = 0; p < 4; p++) acc[mt][p] = 0.f;

        for (int t = 0; t < NKSTEP; t++) {
            const int k0 = t * 16;
            uint4 B = *(const uint4*)(g_WkPack + (((size_t)(t * 32 + lane)) * 8 + wn) * 4);
            #pragma unroll
            for (int mt = 0; mt < 2; mt++) {
                int r = wm * 32 + mt * 16 + rq;
                unsigned ah0 = *(const unsigned*)(sAh + (size_t)r * AST + k0 + kc);
                unsigned ah1 = *(const unsigned*)(sAh + (size_t)(r + 8) * AST + k0 + kc);
                unsigned ah2 = *(const unsigned*)(sAh + (size_t)r * AST + k0 + kc + 8);
                unsigned ah3 = *(const unsigned*)(sAh + (size_t)(r + 8) * AST + k0 + kc + 8);
                unsigned al0 = *(const unsigned*)(sAl + (size_t)r * AST + k0 + kc);
                unsigned al1 = *(const unsigned*)(sAl + (size_t)(r + 8) * AST + k0 + kc);
                unsigned al2 = *(const unsigned*)(sAl + (size_t)r * AST + k0 + kc + 8);
                unsigned al3 = *(const unsigned*)(sAl + (size_t)(r + 8) * AST + k0 + kc + 8);
                mma_bf16(acc[mt], ah0, ah1, ah2, ah3, B.x, B.y);
                mma_bf16(acc[mt], al0, al1, al2, al3, B.x, B.y);
                mma_bf16(acc[mt], ah0, ah1, ah2, ah3, B.z, B.w);
            }
        }

        int oc = wn * 8 + kc;
        float bk0 = (oc < NKH)     ? bk[oc]     : 0.f;
        float bk1 = (oc + 1 < NKH) ? bk[oc + 1] : 0.f;
        #pragma unroll
        for (int mt = 0; mt < 2; mt++) {
            int r = wm * 32 + mt * 16 + rq;
            sL[r * NKHP + oc]           = acc[mt][0] + bk0;
            sL[r * NKHP + oc + 1]       = acc[mt][1] + bk1;
            sL[(r + 8) * NKHP + oc]     = acc[mt][2] + bk0;
            sL[(r + 8) * NKHP + oc + 1] = acc[mt][3] + bk1;
        }
    }
    __syncthreads();

    // ---- P3: softmax over K=9 taps per (row, head) ----
    if (tid < TSR * NH) {
        int r = tid / NH, h = tid % NH;
        float* p = sL + r * NKHP + h * NK;
        float m = p[0];
        #pragma unroll
        for (int k = 1; k < NK; k++) m = fmaxf(m, p[k]);
        float e[NK], ssum = 0.f;
        #pragma unroll
        for (int k = 0; k < NK; k++) { e[k] = __expf(p[k] - m); ssum += e[k]; }
        float inv = 1.0f / ssum;
        #pragma unroll
        for (int k = 0; k < NK; k++) p[k] = e[k] * inv;
    }
    __syncthreads();

    // ---- P4: conv in two 32-row passes; overwrite planes with hi/lo split ----
    {
        const float* vb = v + (size_t)b * NS * ND;
        #pragma unroll
        for (int half = 0; half < 2; half++) {
            int gbase = s0 - NPAD + 32 * half;
            float4* sv4 = (float4*)sV;
            for (int i = tid; i < VR * ND / 4; i += NTH) {
                int rr = i / (ND / 4);
                int gr = gbase + rr;
                float4 val = make_float4(0.f, 0.f, 0.f, 0.f);
                if (gr >= 0 && gr < NS)
                    val = ((const float4*)(vb + (size_t)gr * ND))[i % (ND / 4)];
                sv4[i] = val;
            }
            __syncthreads();

            for (int i = tid; i < 32 * (ND / 2); i += NTH) {
                int rl = i / (ND / 2);          // 0..31
                int pi = i % (ND / 2);
                int c0 = 2 * pi;
                int r  = 32 * half + rl;        // block-local row
                const float* dkp = sL + r * NKHP + (c0 >> 6) * NK;
                float acc0 = 0.f, acc1 = 0.f;
                #pragma unroll
                for (int k = 0; k < NK; k++) {
                    float2 vv = *(const float2*)&sV[(rl + k) * ND + c0];
                    float dk = dkp[k];
                    acc0 = fmaf(dk, vv.x, acc0);
                    acc1 = fmaf(dk, vv.y, acc1);
                }
                __nv_bfloat162 hi = __floats2bfloat162_rn(acc0, acc1);
                float h0 = __bfloat162float(__low2bfloat16(hi));
                float h1 = __bfloat162float(__high2bfloat16(hi));
                __nv_bfloat162 lo = __floats2bfloat162_rn(acc0 - h0, acc1 - h1);
                *(unsigned*)&sAh[r * AST + c0] = *reinterpret_cast<unsigned*>(&hi);
                *(unsigned*)&sAl[r * AST + c0] = *reinterpret_cast<unsigned*>(&lo);
            }
            __syncthreads();
        }
    }

    // ---- P5: out[64 x 384] = A @ Wp^T + bp (A frags via LDS) ----
    {
        const int warp_m = wrp & 1;
        const int warp_n = wrp >> 1;
        const int rb     = warp_m * 32;
        const int rq     = lane >> 2;
        const int kc     = (lane & 3) * 2;

        float acc[2][NJT][4];
        #pragma unroll
        for (int mt = 0; mt < 2; mt++)
            #pragma unroll
            for (int j = 0; j < NJT; j++)
                #pragma unroll
                for (int p = 0; p < 4; p++) acc[mt][j][p] = 0.f;

        for (int t = 0; t < NKSTEP; t++) {
            const int k0 = t * 16;
            unsigned ah[2][4], al[2][4];
            #pragma unroll
            for (int mt = 0; mt < 2; mt++) {
                int r = rb + mt * 16 + rq;
                ah[mt][0] = *(const unsigned*)(sAh + (size_t)r * AST + k0 + kc);
                ah[mt][1] = *(const unsigned*)(sAh + (size_t)(r + 8) * AST + k0 + kc);
                ah[mt][2] = *(const unsigned*)(sAh + (size_t)r * AST + k0 + kc + 8);
                ah[mt][3] = *(const unsigned*)(sAh + (size_t)(r + 8) * AST + k0 + kc + 8);
                al[mt][0] = *(const unsigned*)(sAl + (size_t)r * AST + k0 + kc);
                al[mt][1] = *(const unsigned*)(sAl + (size_t)(r + 8) * AST + k0 + kc);
                al[mt][2] = *(const unsigned*)(sAl + (size_t)r * AST + k0 + kc + 8);
                al[mt][3] = *(const unsigned*)(sAl + (size_t)(r + 8) * AST + k0 + kc + 8);
            }
            const uint4* bptr =
                (const uint4*)(g_Bpack + ((size_t)((t * NCB + warp_n) * 32 + lane)) * (NJT * 4));
            #pragma unroll
            for (int j = 0; j < NJT; j++) {
                uint4 B = bptr[j];
                #pragma unroll
                for (int mt = 0; mt < 2; mt++) {
                    mma_bf16(acc[mt][j], ah[mt][0], ah[mt][1], ah[mt][2], ah[mt][3], B.x, B.y);
                    mma_bf16(acc[mt][j], al[mt][0], al[mt][1], al[mt][2], al[mt][3], B.x, B.y);
                    mma_bf16(acc[mt][j], ah[mt][0], ah[mt][1], ah[mt][2], ah[mt][3], B.z, B.w);
                }
            }
        }

        const int nbase = warp_n * 48;
        float* ob = out + ((size_t)b * NS + s0) * NOUT;
        #pragma unroll
        for (int j = 0; j < NJT; j++) {
            int c = nbase + j * 8 + kc;
            float2 bb = *(const float2*)&bp[c];
            #pragma unroll
            for (int mt = 0; mt < 2; mt++) {
                size_t R = (size_t)(rb + mt * 16 + rq);
                float2 lo = make_float2(acc[mt][j][0] + bb.x, acc[mt][j][1] + bb.y);
                float2 hi = make_float2(acc[mt][j][2] + bb.x, acc[mt][j][3] + bb.y);
                *(float2*)&ob[R * NOUT + c]       = lo;
                *(float2*)&ob[(R + 8) * NOUT + c] = hi;
            }
        }
    }
}

extern "C" void kernel_launch(void* const* d_in, const int* in_sizes, int n_in,
                              void* d_out, int out_size) {
    const float* q  = (const float*)d_in[0];
    const float* ks = (const float*)d_in[1];
    const float* v  = (const float*)d_in[2];
    const float* Wk = (const float*)d_in[3];
    const float* bk = (const float*)d_in[4];
    const float* Wp = (const float*)d_in[5];
    const float* bp = (const float*)d_in[6];
    float* out = (float*)d_out;

    (void)in_sizes; (void)n_in; (void)out_size;

    prep_kernel<<<(BPACK_WORDS + 255) / 256, 256>>>(Wp, Wk);

    const int smem_bytes = SMEM_FLOATS * (int)sizeof(float);  // 178176
    cudaFuncSetAttribute(sdca_fused, cudaFuncAttributeMaxDynamicSharedMemorySize, smem_bytes);
    sdca_fused<<<NB * (NS / TSR), NTH, smem_bytes>>>(q, ks, v, bk, bp, out);
}

// round 7
// speedup vs baseline: 3.0716x; 1.0058x over previous
#include <cuda_runtime.h>
#include <cuda_bf16.h>
#include <cstddef>
#include <cstdint>

// Problem constants
#define NB    16
#define NS    1024
#define ND    384      // H * HD
#define NH    6
#define NHD   64
#define NK    9
#define NKH   54       // K * H
#define NKHP  64       // padded logits width
#define NOUT  384
#define NPAD  4        // K/2

// Fused kernel tiling
#define TSR      64    // seq rows per block
#define NTH      512
#define AST      392   // bf16 plane row stride (halfs) — conflict-free LDSM
#define VR       40    // v rows staged per conv half-pass (32 + 8 halo)

#define NKSTEP   24
#define NJT      6     // n8 tiles per warp in P5
#define NCB      8     // col blocks of 48

// Wp pack: [t(24)][cb(8)][lane(32)][j(6)][p(4)]
#define BPACK_WORDS (NKSTEP * NCB * 32 * NJT * 4)      // 147456
// Wk pack: [t(24)][lane(32)][j(8)][p(4)]
#define WKPACK_WORDS (NKSTEP * 32 * 8 * 4)             // 24576

// ---------------- bf16 mma ----------------
__device__ __forceinline__ void mma_bf16(float* c,
                                         unsigned a0, unsigned a1,
                                         unsigned a2, unsigned a3,
                                         unsigned b0, unsigned b1) {
    asm volatile(
        "mma.sync.aligned.m16n8k16.row.col.f32.bf16.bf16.f32 "
        "{%0,%1,%2,%3}, {%4,%5,%6,%7}, {%8,%9}, {%0,%1,%2,%3};\n"
        : "+f"(c[0]), "+f"(c[1]), "+f"(c[2]), "+f"(c[3])
        : "r"(a0), "r"(a1), "r"(a2), "r"(a3), "r"(b0), "r"(b1));
}

// ---------------- ldmatrix x4 (16x16 bf16 A tile) ----------------
__device__ __forceinline__ void ldsm_x4(unsigned& r0, unsigned& r1,
                                        unsigned& r2, unsigned& r3,
                                        unsigned addr) {
    asm volatile(
        "ldmatrix.sync.aligned.m8n8.x4.shared.b16 {%0,%1,%2,%3}, [%4];"
        : "=r"(r0), "=r"(r1), "=r"(r2), "=r"(r3) : "r"(addr));
}

__device__ __forceinline__ unsigned smem_u32(const void* p) {
    unsigned a;
    asm("{ .reg .u64 t; cvta.to.shared.u64 t, %1; cvt.u32.u64 %0, t; }"
        : "=r"(a) : "l"(p));
    return a;
}

__device__ unsigned int g_Bpack[BPACK_WORDS];
__device__ unsigned int g_WkPack[WKPACK_WORDS];

__device__ __forceinline__ unsigned split_pack(float x, float y, int p) {
    if (p < 2) {
        __nv_bfloat162 h = __floats2bfloat162_rn(x, y);
        return *reinterpret_cast<unsigned*>(&h);
    } else {
        float xh = __bfloat162float(__float2bfloat16_rn(x));
        float yh = __bfloat162float(__float2bfloat16_rn(y));
        __nv_bfloat162 h = __floats2bfloat162_rn(x - xh, y - yh);
        return *reinterpret_cast<unsigned*>(&h);
    }
}

__global__ void prep_kernel(const float* __restrict__ Wp,
                            const float* __restrict__ Wk) {
    int i = blockIdx.x * blockDim.x + threadIdx.x;
    if (i < BPACK_WORDS) {
        int p  = i & 3;
        int j  = (i >> 2) % NJT;
        int l  = (i / (NJT * 4)) & 31;
        int cb = (i / (NJT * 4 * 32)) % NCB;
        int t  =  i / (NJT * 4 * 32 * NCB);
        int o  = cb * 48 + j * 8 + (l >> 2);
        int k0 = t * 16 + (l & 3) * 2 + ((p & 1) ? 8 : 0);
        g_Bpack[i] = split_pack(Wp[o * ND + k0], Wp[o * ND + k0 + 1], p);
    }
    if (i < WKPACK_WORDS) {
        int p  = i & 3;
        int j  = (i >> 2) & 7;
        int l  = (i >> 5) & 31;
        int t  =  i >> 10;
        int o  = j * 8 + (l >> 2);
        int k0 = t * 16 + (l & 3) * 2 + ((p & 1) ? 8 : 0);
        float x = (o < NKH) ? Wk[o * ND + k0]     : 0.f;
        float y = (o < NKH) ? Wk[o * ND + k0 + 1] : 0.f;
        g_WkPack[i] = split_pack(x, y, p);
    }
}

// ============================================================================
// Fused kernel: one block = (batch, 64 seq rows)
// smem (floats, total 44544 = 178176 B):
//   planes [0, 25088):       sAh/sAl 64 x 392 halfs each
//   sV     [25088, 40448):   40 x 384 fp32
//   sL     [40448, 44544):   64 x 64 fp32
// ============================================================================
#define SMEM_FLOATS 44544

__global__ __launch_bounds__(NTH, 1) void sdca_fused(
    const float* __restrict__ q,
    const float* __restrict__ ks,
    const float* __restrict__ v,
    const float* __restrict__ bk,
    const float* __restrict__ bp,
    float* __restrict__ out)
{
    extern __shared__ float smem[];
    __nv_bfloat16* sAh = (__nv_bfloat16*)smem;           // 64 x AST halfs
    __nv_bfloat16* sAl = sAh + TSR * AST;
    float* sV = smem + 25088;
    float* sL = smem + 40448;

    const int tid  = threadIdx.x;
    const int lane = tid & 31;
    const int wrp  = tid >> 5;
    const int b    = blockIdx.x / (NS / TSR);
    const int s0   = (blockIdx.x % (NS / TSR)) * TSR;

    // ldmatrix lane address components: row = (lane & 15), colhalf = (lane >> 4)*8
    const int lm_row = lane & 15;
    const int lm_col = (lane >> 4) * 8;

    // ---- P1: planes = bf16 hi/lo split of q*ks ----
    {
        const float4* qb = (const float4*)(q  + ((size_t)b * NS + s0) * ND);
        const float4* kb = (const float4*)(ks + ((size_t)b * NS + s0) * ND);
        #pragma unroll
        for (int i = tid; i < TSR * (ND / 4); i += NTH) {
            int r  = i / (ND / 4);
            int c4 = (i % (ND / 4)) * 4;
            float4 qq = qb[i], kk = kb[i];
            float p0 = qq.x * kk.x, p1 = qq.y * kk.y;
            float p2 = qq.z * kk.z, p3 = qq.w * kk.w;
            __nv_bfloat162 h01 = __floats2bfloat162_rn(p0, p1);
            __nv_bfloat162 h23 = __floats2bfloat162_rn(p2, p3);
            float h0 = __bfloat162float(__low2bfloat16(h01));
            float h1 = __bfloat162float(__high2bfloat16(h01));
            float h2 = __bfloat162float(__low2bfloat16(h23));
            float h3 = __bfloat162float(__high2bfloat16(h23));
            __nv_bfloat162 l01 = __floats2bfloat162_rn(p0 - h0, p1 - h1);
            __nv_bfloat162 l23 = __floats2bfloat162_rn(p2 - h2, p3 - h3);
            uint2 wh, wl;
            wh.x = *reinterpret_cast<unsigned*>(&h01);
            wh.y = *reinterpret_cast<unsigned*>(&h23);
            wl.x = *reinterpret_cast<unsigned*>(&l01);
            wl.y = *reinterpret_cast<unsigned*>(&l23);
            *(uint2*)&sAh[r * AST + c4] = wh;
            *(uint2*)&sAl[r * AST + c4] = wl;
        }
    }
    __syncthreads();

    // ---- P2: logits[64 x 64] via bf16 3-split mma + ldmatrix ----
    {
        const int wm = wrp & 1;
        const int wn = wrp >> 1;
        const int rq = lane >> 2;
        const int kc = (lane & 3) * 2;
        float acc[2][4];
        #pragma unroll
        for (int mt = 0; mt < 2; mt++)
            #pragma unroll
            for (int p = 0; p < 4; p++) acc[mt][p] = 0.f;

        // per-warp ldmatrix base addresses (advance +32B per k-step)
        unsigned ah_base[2], al_base[2];
        #pragma unroll
        for (int mt = 0; mt < 2; mt++) {
            int r = wm * 32 + mt * 16 + lm_row;
            ah_base[mt] = smem_u32(sAh + (size_t)r * AST + lm_col);
            al_base[mt] = smem_u32(sAl + (size_t)r * AST + lm_col);
        }

        for (int t = 0; t < NKSTEP; t++) {
            uint4 B = *(const uint4*)(g_WkPack + (((size_t)(t * 32 + lane)) * 8 + wn) * 4);
            #pragma unroll
            for (int mt = 0; mt < 2; mt++) {
                unsigned ah0, ah1, ah2, ah3, al0, al1, al2, al3;
                ldsm_x4(ah0, ah1, ah2, ah3, ah_base[mt] + t * 32);
                ldsm_x4(al0, al1, al2, al3, al_base[mt] + t * 32);
                mma_bf16(acc[mt], ah0, ah1, ah2, ah3, B.x, B.y);
                mma_bf16(acc[mt], al0, al1, al2, al3, B.x, B.y);
                mma_bf16(acc[mt], ah0, ah1, ah2, ah3, B.z, B.w);
            }
        }

        int oc = wn * 8 + kc;
        float bk0 = (oc < NKH)     ? bk[oc]     : 0.f;
        float bk1 = (oc + 1 < NKH) ? bk[oc + 1] : 0.f;
        #pragma unroll
        for (int mt = 0; mt < 2; mt++) {
            int r = wm * 32 + mt * 16 + rq;
            sL[r * NKHP + oc]           = acc[mt][0] + bk0;
            sL[r * NKHP + oc + 1]       = acc[mt][1] + bk1;
            sL[(r + 8) * NKHP + oc]     = acc[mt][2] + bk0;
            sL[(r + 8) * NKHP + oc + 1] = acc[mt][3] + bk1;
        }
    }
    __syncthreads();

    // ---- P3: softmax over K=9 taps per (row, head) ----
    if (tid < TSR * NH) {
        int r = tid / NH, h = tid % NH;
        float* p = sL + r * NKHP + h * NK;
        float m = p[0];
        #pragma unroll
        for (int k = 1; k < NK; k++) m = fmaxf(m, p[k]);
        float e[NK], ssum = 0.f;
        #pragma unroll
        for (int k = 0; k < NK; k++) { e[k] = __expf(p[k] - m); ssum += e[k]; }
        float inv = 1.0f / ssum;
        #pragma unroll
        for (int k = 0; k < NK; k++) p[k] = e[k] * inv;
    }
    __syncthreads();

    // ---- P4: conv in two 32-row passes; overwrite planes with hi/lo split ----
    {
        const float* vb = v + (size_t)b * NS * ND;
        #pragma unroll
        for (int half = 0; half < 2; half++) {
            int gbase = s0 - NPAD + 32 * half;
            float4* sv4 = (float4*)sV;
            for (int i = tid; i < VR * ND / 4; i += NTH) {
                int rr = i / (ND / 4);
                int gr = gbase + rr;
                float4 val = make_float4(0.f, 0.f, 0.f, 0.f);
                if (gr >= 0 && gr < NS)
                    val = ((const float4*)(vb + (size_t)gr * ND))[i % (ND / 4)];
                sv4[i] = val;
            }
            __syncthreads();

            for (int i = tid; i < 32 * (ND / 2); i += NTH) {
                int rl = i / (ND / 2);
                int pi = i % (ND / 2);
                int c0 = 2 * pi;
                int r  = 32 * half + rl;
                const float* dkp = sL + r * NKHP + (c0 >> 6) * NK;
                float acc0 = 0.f, acc1 = 0.f;
                #pragma unroll
                for (int k = 0; k < NK; k++) {
                    float2 vv = *(const float2*)&sV[(rl + k) * ND + c0];
                    float dk = dkp[k];
                    acc0 = fmaf(dk, vv.x, acc0);
                    acc1 = fmaf(dk, vv.y, acc1);
                }
                __nv_bfloat162 hi = __floats2bfloat162_rn(acc0, acc1);
                float h0 = __bfloat162float(__low2bfloat16(hi));
                float h1 = __bfloat162float(__high2bfloat16(hi));
                __nv_bfloat162 lo = __floats2bfloat162_rn(acc0 - h0, acc1 - h1);
                *(unsigned*)&sAh[r * AST + c0] = *reinterpret_cast<unsigned*>(&hi);
                *(unsigned*)&sAl[r * AST + c0] = *reinterpret_cast<unsigned*>(&lo);
            }
            __syncthreads();
        }
    }

    // ---- P5: out[64 x 384] = A @ Wp^T + bp (A frags via ldmatrix) ----
    {
        const int warp_m = wrp & 1;
        const int warp_n = wrp >> 1;
        const int rb     = warp_m * 32;
        const int rq     = lane >> 2;
        const int kc     = (lane & 3) * 2;

        float acc[2][NJT][4];
        #pragma unroll
        for (int mt = 0; mt < 2; mt++)
            #pragma unroll
            for (int j = 0; j < NJT; j++)
                #pragma unroll
                for (int p = 0; p < 4; p++) acc[mt][j][p] = 0.f;

        unsigned ah_base[2], al_base[2];
        #pragma unroll
        for (int mt = 0; mt < 2; mt++) {
            int r = rb + mt * 16 + lm_row;
            ah_base[mt] = smem_u32(sAh + (size_t)r * AST + lm_col);
            al_base[mt] = smem_u32(sAl + (size_t)r * AST + lm_col);
        }

        for (int t = 0; t < NKSTEP; t++) {
            unsigned ah[2][4], al[2][4];
            #pragma unroll
            for (int mt = 0; mt < 2; mt++) {
                ldsm_x4(ah[mt][0], ah[mt][1], ah[mt][2], ah[mt][3], ah_base[mt] + t * 32);
                ldsm_x4(al[mt][0], al[mt][1], al[mt][2], al[mt][3], al_base[mt] + t * 32);
            }
            const uint4* bptr =
                (const uint4*)(g_Bpack + ((size_t)((t * NCB + warp_n) * 32 + lane)) * (NJT * 4));
            #pragma unroll
            for (int j = 0; j < NJT; j++) {
                uint4 B = bptr[j];
                #pragma unroll
                for (int mt = 0; mt < 2; mt++) {
                    mma_bf16(acc[mt][j], ah[mt][0], ah[mt][1], ah[mt][2], ah[mt][3], B.x, B.y);
                    mma_bf16(acc[mt][j], al[mt][0], al[mt][1], al[mt][2], al[mt][3], B.x, B.y);
                    mma_bf16(acc[mt][j], ah[mt][0], ah[mt][1], ah[mt][2], ah[mt][3], B.z, B.w);
                }
            }
        }

        const int nbase = warp_n * 48;
        float* ob = out + ((size_t)b * NS + s0) * NOUT;
        #pragma unroll
        for (int j = 0; j < NJT; j++) {
            int c = nbase + j * 8 + kc;
            float2 bb = *(const float2*)&bp[c];
            #pragma unroll
            for (int mt = 0; mt < 2; mt++) {
                size_t R = (size_t)(rb + mt * 16 + rq);
                float2 lo = make_float2(acc[mt][j][0] + bb.x, acc[mt][j][1] + bb.y);
                float2 hi = make_float2(acc[mt][j][2] + bb.x, acc[mt][j][3] + bb.y);
                *(float2*)&ob[R * NOUT + c]       = lo;
                *(float2*)&ob[(R + 8) * NOUT + c] = hi;
            }
        }
    }
}

extern "C" void kernel_launch(void* const* d_in, const int* in_sizes, int n_in,
                              void* d_out, int out_size) {
    const float* q  = (const float*)d_in[0];
    const float* ks = (const float*)d_in[1];
    const float* v  = (const float*)d_in[2];
    const float* Wk = (const float*)d_in[3];
    const float* bk = (const float*)d_in[4];
    const float* Wp = (const float*)d_in[5];
    const float* bp = (const float*)d_in[6];
    float* out = (float*)d_out;

    (void)in_sizes; (void)n_in; (void)out_size;

    prep_kernel<<<(BPACK_WORDS + 255) / 256, 256>>>(Wp, Wk);

    const int smem_bytes = SMEM_FLOATS * (int)sizeof(float);  // 178176
    cudaFuncSetAttribute(sdca_fused, cudaFuncAttributeMaxDynamicSharedMemorySize, smem_bytes);
    sdca_fused<<<NB * (NS / TSR), NTH, smem_bytes>>>(q, ks, v, bk, bp, out);
}

// round 8
// speedup vs baseline: 3.3379x; 1.0867x over previous
#include <cuda_runtime.h>
#include <cuda_bf16.h>
#include <cstddef>
#include <cstdint>

// Problem constants
#define NB    16
#define NS    1024
#define ND    384      // H * HD
#define NH    6
#define NHD   64
#define NK    9
#define NKH   54       // K * H
#define NKHP  64       // padded logits width
#define NOUT  384
#define NPAD  4        // K/2

// Fused kernel tiling
#define TSR      64    // seq rows per block
#define NTH      512
#define AST      392   // bf16 plane row stride (halfs) — conflict-free LDSM
#define VR       40    // v rows staged per conv half-pass (32 + 8 halo)

#define NKSTEP   24
#define NJT      6     // n8 tiles per warp in P5
#define NCB      8     // col blocks of 48

// Wp pack: [t(24)][cb(8)][lane(32)][j(6)][p(4)]
#define BPACK_WORDS (NKSTEP * NCB * 32 * NJT * 4)      // 147456
// Wk pack: [t(24)][lane(32)][j(8)][p(4)]
#define WKPACK_WORDS (NKSTEP * 32 * 8 * 4)             // 24576

// ---------------- bf16 mma ----------------
__device__ __forceinline__ void mma_bf16(float* c,
                                         unsigned a0, unsigned a1,
                                         unsigned a2, unsigned a3,
                                         unsigned b0, unsigned b1) {
    asm volatile(
        "mma.sync.aligned.m16n8k16.row.col.f32.bf16.bf16.f32 "
        "{%0,%1,%2,%3}, {%4,%5,%6,%7}, {%8,%9}, {%0,%1,%2,%3};\n"
        : "+f"(c[0]), "+f"(c[1]), "+f"(c[2]), "+f"(c[3])
        : "r"(a0), "r"(a1), "r"(a2), "r"(a3), "r"(b0), "r"(b1));
}

__device__ __forceinline__ void ldsm_x4(unsigned& r0, unsigned& r1,
                                        unsigned& r2, unsigned& r3,
                                        unsigned addr) {
    asm volatile(
        "ldmatrix.sync.aligned.m8n8.x4.shared.b16 {%0,%1,%2,%3}, [%4];"
        : "=r"(r0), "=r"(r1), "=r"(r2), "=r"(r3) : "r"(addr));
}

__device__ __forceinline__ unsigned smem_u32(const void* p) {
    unsigned a;
    asm("{ .reg .u64 t; cvta.to.shared.u64 t, %1; cvt.u32.u64 %0, t; }"
        : "=r"(a) : "l"(p));
    return a;
}

__device__ __forceinline__ void cp_async16(unsigned dst, const void* src, int src_bytes) {
    asm volatile("cp.async.cg.shared.global [%0], [%1], 16, %2;\n"
                 :: "r"(dst), "l"(src), "r"(src_bytes));
}
__device__ __forceinline__ void cp_async_commit() {
    asm volatile("cp.async.commit_group;\n" ::: "memory");
}
__device__ __forceinline__ void cp_async_wait0() {
    asm volatile("cp.async.wait_group 0;\n" ::: "memory");
}

__device__ unsigned int g_Bpack[BPACK_WORDS];
__device__ unsigned int g_WkPack[WKPACK_WORDS];

__device__ __forceinline__ unsigned split_pack(float x, float y, int p) {
    if (p < 2) {
        __nv_bfloat162 h = __floats2bfloat162_rn(x, y);
        return *reinterpret_cast<unsigned*>(&h);
    } else {
        float xh = __bfloat162float(__float2bfloat16_rn(x));
        float yh = __bfloat162float(__float2bfloat16_rn(y));
        __nv_bfloat162 h = __floats2bfloat162_rn(x - xh, y - yh);
        return *reinterpret_cast<unsigned*>(&h);
    }
}

__global__ void prep_kernel(const float* __restrict__ Wp,
                            const float* __restrict__ Wk) {
    int i = blockIdx.x * blockDim.x + threadIdx.x;
    if (i < BPACK_WORDS) {
        int p  = i & 3;
        int j  = (i >> 2) % NJT;
        int l  = (i / (NJT * 4)) & 31;
        int cb = (i / (NJT * 4 * 32)) % NCB;
        int t  =  i / (NJT * 4 * 32 * NCB);
        int o  = cb * 48 + j * 8 + (l >> 2);
        int k0 = t * 16 + (l & 3) * 2 + ((p & 1) ? 8 : 0);
        g_Bpack[i] = split_pack(Wp[o * ND + k0], Wp[o * ND + k0 + 1], p);
    }
    if (i < WKPACK_WORDS) {
        int p  = i & 3;
        int j  = (i >> 2) & 7;
        int l  = (i >> 5) & 31;
        int t  =  i >> 10;
        int o  = j * 8 + (l >> 2);
        int k0 = t * 16 + (l & 3) * 2 + ((p & 1) ? 8 : 0);
        float x = (o < NKH) ? Wk[o * ND + k0]     : 0.f;
        float y = (o < NKH) ? Wk[o * ND + k0 + 1] : 0.f;
        g_WkPack[i] = split_pack(x, y, p);
    }
}

// ============================================================================
// Fused kernel: one block = (batch, 64 seq rows)
// smem (floats, total 44544 = 178176 B):
//   planes [0, 25088):       sAh/sAl 64 x 392 halfs each
//   sV     [25088, 40448):   40 x 384 fp32
//   sL     [40448, 44544):   64 x 64 fp32
// ============================================================================
#define SMEM_FLOATS 44544

__global__ __launch_bounds__(NTH, 1) void sdca_fused(
    const float* __restrict__ q,
    const float* __restrict__ ks,
    const float* __restrict__ v,
    const float* __restrict__ bk,
    const float* __restrict__ bp,
    float* __restrict__ out)
{
    extern __shared__ float smem[];
    __nv_bfloat16* sAh = (__nv_bfloat16*)smem;           // 64 x AST halfs
    __nv_bfloat16* sAl = sAh + TSR * AST;
    float* sV = smem + 25088;
    float* sL = smem + 40448;

    const int tid  = threadIdx.x;
    const int lane = tid & 31;
    const int wrp  = tid >> 5;
    const int b    = blockIdx.x / (NS / TSR);
    const int s0   = (blockIdx.x % (NS / TSR)) * TSR;

    const int lm_row = lane & 15;
    const int lm_col = (lane >> 4) * 8;

    const float* vb = v + (size_t)b * NS * ND;

    // ---- P0: cp.async prefetch of conv pass-1 v window (rows s0-4 .. s0+35) ----
    {
        const unsigned sv_base = smem_u32(sV);
        #pragma unroll
        for (int i = tid; i < VR * (ND / 4); i += NTH) {
            int rr = i / (ND / 4);
            int cc = i % (ND / 4);
            int gr = s0 - NPAD + rr;
            int ok = (gr >= 0 && gr < NS) ? 16 : 0;
            const float4* src = (const float4*)(vb + (size_t)max(gr, 0) * ND) + cc;
            cp_async16(sv_base + i * 16, src, ok);
        }
        cp_async_commit();
    }

    // ---- P1: planes = bf16 hi/lo split of q*ks ----
    {
        const float4* qb = (const float4*)(q  + ((size_t)b * NS + s0) * ND);
        const float4* kb = (const float4*)(ks + ((size_t)b * NS + s0) * ND);
        #pragma unroll
        for (int i = tid; i < TSR * (ND / 4); i += NTH) {
            int r  = i / (ND / 4);
            int c4 = (i % (ND / 4)) * 4;
            float4 qq = qb[i], kk = kb[i];
            float p0 = qq.x * kk.x, p1 = qq.y * kk.y;
            float p2 = qq.z * kk.z, p3 = qq.w * kk.w;
            __nv_bfloat162 h01 = __floats2bfloat162_rn(p0, p1);
            __nv_bfloat162 h23 = __floats2bfloat162_rn(p2, p3);
            float h0 = __bfloat162float(__low2bfloat16(h01));
            float h1 = __bfloat162float(__high2bfloat16(h01));
            float h2 = __bfloat162float(__low2bfloat16(h23));
            float h3 = __bfloat162float(__high2bfloat16(h23));
            __nv_bfloat162 l01 = __floats2bfloat162_rn(p0 - h0, p1 - h1);
            __nv_bfloat162 l23 = __floats2bfloat162_rn(p2 - h2, p3 - h3);
            uint2 wh, wl;
            wh.x = *reinterpret_cast<unsigned*>(&h01);
            wh.y = *reinterpret_cast<unsigned*>(&h23);
            wl.x = *reinterpret_cast<unsigned*>(&l01);
            wl.y = *reinterpret_cast<unsigned*>(&l23);
            *(uint2*)&sAh[r * AST + c4] = wh;
            *(uint2*)&sAl[r * AST + c4] = wl;
        }
    }
    __syncthreads();

    // ---- P2: logits[64 x 64] via bf16 3-split mma + ldmatrix ----
    {
        const int wm = wrp & 1;
        const int wn = wrp >> 1;
        const int rq = lane >> 2;
        const int kc = (lane & 3) * 2;
        float acc[2][4];
        #pragma unroll
        for (int mt = 0; mt < 2; mt++)
            #pragma unroll
            for (int p = 0; p < 4; p++) acc[mt][p] = 0.f;

        unsigned ah_base[2], al_base[2];
        #pragma unroll
        for (int mt = 0; mt < 2; mt++) {
            int r = wm * 32 + mt * 16 + lm_row;
            ah_base[mt] = smem_u32(sAh + (size_t)r * AST + lm_col);
            al_base[mt] = smem_u32(sAl + (size_t)r * AST + lm_col);
        }

        for (int t = 0; t < NKSTEP; t++) {
            uint4 B = *(const uint4*)(g_WkPack + (((size_t)(t * 32 + lane)) * 8 + wn) * 4);
            #pragma unroll
            for (int mt = 0; mt < 2; mt++) {
                unsigned ah0, ah1, ah2, ah3, al0, al1, al2, al3;
                ldsm_x4(ah0, ah1, ah2, ah3, ah_base[mt] + t * 32);
                ldsm_x4(al0, al1, al2, al3, al_base[mt] + t * 32);
                mma_bf16(acc[mt], ah0, ah1, ah2, ah3, B.x, B.y);
                mma_bf16(acc[mt], al0, al1, al2, al3, B.x, B.y);
                mma_bf16(acc[mt], ah0, ah1, ah2, ah3, B.z, B.w);
            }
        }

        int oc = wn * 8 + kc;
        float bk0 = (oc < NKH)     ? bk[oc]     : 0.f;
        float bk1 = (oc + 1 < NKH) ? bk[oc + 1] : 0.f;
        #pragma unroll
        for (int mt = 0; mt < 2; mt++) {
            int r = wm * 32 + mt * 16 + rq;
            sL[r * NKHP + oc]           = acc[mt][0] + bk0;
            sL[r * NKHP + oc + 1]       = acc[mt][1] + bk1;
            sL[(r + 8) * NKHP + oc]     = acc[mt][2] + bk0;
            sL[(r + 8) * NKHP + oc + 1] = acc[mt][3] + bk1;
        }
    }
    __syncthreads();

    // ---- P3: softmax over K=9 taps per (row, head) ----
    if (tid < TSR * NH) {
        int r = tid / NH, h = tid % NH;
        float* p = sL + r * NKHP + h * NK;
        float m = p[0];
        #pragma unroll
        for (int k = 1; k < NK; k++) m = fmaxf(m, p[k]);
        float e[NK], ssum = 0.f;
        #pragma unroll
        for (int k = 0; k < NK; k++) { e[k] = __expf(p[k] - m); ssum += e[k]; }
        float inv = 1.0f / ssum;
        #pragma unroll
        for (int k = 0; k < NK; k++) p[k] = e[k] * inv;
    }
    cp_async_wait0();           // pass-1 v window resident
    __syncthreads();

    // ---- P4: conv, warp-unit = (head, 8-row block), sliding v window ----
    // Per half: 24 units (4 row-blocks x 6 heads). Lane = column pair in head.
    {
        #pragma unroll
        for (int half = 0; half < 2; half++) {
            if (half == 1) {
                // stage pass-2 v rows [s0+28, s0+68) (sync; prior reads done)
                __syncthreads();
                int gbase = s0 - NPAD + 32;
                float4* sv4 = (float4*)sV;
                for (int i = tid; i < VR * ND / 4; i += NTH) {
                    int rr = i / (ND / 4);
                    int gr = gbase + rr;
                    float4 val = make_float4(0.f, 0.f, 0.f, 0.f);
                    if (gr >= 0 && gr < NS)
                        val = ((const float4*)(vb + (size_t)gr * ND))[i % (ND / 4)];
                    sv4[i] = val;
                }
                __syncthreads();
            }

            #pragma unroll
            for (int it = 0; it < 2; it++) {
                int uid = wrp + 16 * it;
                if (uid < 24) {
                    int h  = uid % NH;
                    int rb = uid / NH;          // 0..3 (8-row block)
                    int c0 = h * NHD + lane * 2;
                    int r0 = rb * 8;            // local within half

                    // sliding v window: 16 float2
                    float2 w[16];
                    #pragma unroll
                    for (int j = 0; j < 16; j++)
                        w[j] = *(const float2*)&sV[(r0 + j) * ND + c0];

                    #pragma unroll
                    for (int i = 0; i < 8; i++) {
                        int r = half * 32 + r0 + i;      // block-local row
                        const float* dkp = sL + r * NKHP + h * NK;
                        float a0 = 0.f, a1 = 0.f;
                        #pragma unroll
                        for (int k = 0; k < NK; k++) {
                            float dk = dkp[k];           // broadcast LDS
                            a0 = fmaf(dk, w[i + k].x, a0);
                            a1 = fmaf(dk, w[i + k].y, a1);
                        }
                        __nv_bfloat162 hi = __floats2bfloat162_rn(a0, a1);
                        float h0 = __bfloat162float(__low2bfloat16(hi));
                        float h1 = __bfloat162float(__high2bfloat16(hi));
                        __nv_bfloat162 lo = __floats2bfloat162_rn(a0 - h0, a1 - h1);
                        *(unsigned*)&sAh[r * AST + c0] = *reinterpret_cast<unsigned*>(&hi);
                        *(unsigned*)&sAl[r * AST + c0] = *reinterpret_cast<unsigned*>(&lo);
                    }
                }
            }
        }
        __syncthreads();
    }

    // ---- P5: out[64 x 384] = A @ Wp^T + bp (A frags via ldmatrix) ----
    {
        const int warp_m = wrp & 1;
        const int warp_n = wrp >> 1;
        const int rb     = warp_m * 32;
        const int rq     = lane >> 2;
        const int kc     = (lane & 3) * 2;

        float acc[2][NJT][4];
        #pragma unroll
        for (int mt = 0; mt < 2; mt++)
            #pragma unroll
            for (int j = 0; j < NJT; j++)
                #pragma unroll
                for (int p = 0; p < 4; p++) acc[mt][j][p] = 0.f;

        unsigned ah_base[2], al_base[2];
        #pragma unroll
        for (int mt = 0; mt < 2; mt++) {
            int r = rb + mt * 16 + lm_row;
            ah_base[mt] = smem_u32(sAh + (size_t)r * AST + lm_col);
            al_base[mt] = smem_u32(sAl + (size_t)r * AST + lm_col);
        }

        for (int t = 0; t < NKSTEP; t++) {
            unsigned ah[2][4], al[2][4];
            #pragma unroll
            for (int mt = 0; mt < 2; mt++) {
                ldsm_x4(ah[mt][0], ah[mt][1], ah[mt][2], ah[mt][3], ah_base[mt] + t * 32);
                ldsm_x4(al[mt][0], al[mt][1], al[mt][2], al[mt][3], al_base[mt] + t * 32);
            }
            const uint4* bptr =
                (const uint4*)(g_Bpack + ((size_t)((t * NCB + warp_n) * 32 + lane)) * (NJT * 4));
            #pragma unroll
            for (int j = 0; j < NJT; j++) {
                uint4 B = bptr[j];
                #pragma unroll
                for (int mt = 0; mt < 2; mt++) {
                    mma_bf16(acc[mt][j], ah[mt][0], ah[mt][1], ah[mt][2], ah[mt][3], B.x, B.y);
                    mma_bf16(acc[mt][j], al[mt][0], al[mt][1], al[mt][2], al[mt][3], B.x, B.y);
                    mma_bf16(acc[mt][j], ah[mt][0], ah[mt][1], ah[mt][2], ah[mt][3], B.z, B.w);
                }
            }
        }

        const int nbase = warp_n * 48;
        float* ob = out + ((size_t)b * NS + s0) * NOUT;
        #pragma unroll
        for (int j = 0; j < NJT; j++) {
            int c = nbase + j * 8 + kc;
            float2 bb = *(const float2*)&bp[c];
            #pragma unroll
            for (int mt = 0; mt < 2; mt++) {
                size_t R = (size_t)(rb + mt * 16 + rq);
                float2 lo = make_float2(acc[mt][j][0] + bb.x, acc[mt][j][1] + bb.y);
                float2 hi = make_float2(acc[mt][j][2] + bb.x, acc[mt][j][3] + bb.y);
                *(float2*)&ob[R * NOUT + c]       = lo;
                *(float2*)&ob[(R + 8) * NOUT + c] = hi;
            }
        }
    }
}

extern "C" void kernel_launch(void* const* d_in, const int* in_sizes, int n_in,
                              void* d_out, int out_size) {
    const float* q  = (const float*)d_in[0];
    const float* ks = (const float*)d_in[1];
    const float* v  = (const float*)d_in[2];
    const float* Wk = (const float*)d_in[3];
    const float* bk = (const float*)d_in[4];
    const float* Wp = (const float*)d_in[5];
    const float* bp = (const float*)d_in[6];
    float* out = (float*)d_out;

    (void)in_sizes; (void)n_in; (void)out_size;

    prep_kernel<<<(BPACK_WORDS + 255) / 256, 256>>>(Wp, Wk);

    const int smem_bytes = SMEM_FLOATS * (int)sizeof(float);  // 178176
    cudaFuncSetAttribute(sdca_fused, cudaFuncAttributeMaxDynamicSharedMemorySize, smem_bytes);
    sdca_fused<<<NB * (NS / TSR), NTH, smem_bytes>>>(q, ks, v, bk, bp, out);
}